// round 1
// baseline (speedup 1.0000x reference)
#include <cuda_runtime.h>

#define B_  2
#define T_  2048
#define C_  1024
#define H_  16
#define DH  64
#define M_  (B_ * T_)

// Scratch (static device globals — no runtime allocation)
__device__ float g_qkv[(size_t)M_ * 3 * C_];   // [4096, 3072]
__device__ float g_y  [(size_t)M_ * C_];       // [4096, 1024]

// ---------------------------------------------------------------------------
// 128x128x8 register-blocked SGEMM, 256 threads, 8x8 per-thread tile,
// global->reg prefetch to hide load latency.
// A [M,K] row-major, B [K,N] row-major, C [M,N] row-major.
// ---------------------------------------------------------------------------
template<int M, int N, int K>
__device__ __forceinline__ void gemm_body(const float* __restrict__ A,
                                          const float* __restrict__ B,
                                          float* __restrict__ C)
{
    constexpr int BM = 128, BN = 128, BK = 8;
    __shared__ float As[BK][BM];
    __shared__ float Bs[BK][BN];

    const int tid = threadIdx.x;
    const int m0 = blockIdx.y * BM;
    const int n0 = blockIdx.x * BN;

    // A tile loader: thread -> (row ra, k-quad ka)
    const int ra = tid >> 1;            // 0..127
    const int ka = (tid & 1) * 4;       // 0 or 4
    // B tile loader: thread -> (k-row rb, col-quad nb)
    const int rb = tid >> 5;            // 0..7
    const int nb = (tid & 31) * 4;      // 0..124

    const float* Aptr = A + (size_t)(m0 + ra) * K + ka;
    const float* Bptr = B + (size_t)rb * N + n0 + nb;

    float4 aReg = *(const float4*)Aptr;
    float4 bReg = *(const float4*)Bptr;

    const int tx = tid & 15;
    const int ty = tid >> 4;

    float acc[8][8];
    #pragma unroll
    for (int i = 0; i < 8; i++)
        #pragma unroll
        for (int j = 0; j < 8; j++) acc[i][j] = 0.f;

    for (int k0 = 0; k0 < K; k0 += BK) {
        As[ka + 0][ra] = aReg.x;
        As[ka + 1][ra] = aReg.y;
        As[ka + 2][ra] = aReg.z;
        As[ka + 3][ra] = aReg.w;
        *(float4*)&Bs[rb][nb] = bReg;
        __syncthreads();

        if (k0 + BK < K) {
            aReg = *(const float4*)(Aptr + (k0 + BK));
            bReg = *(const float4*)(Bptr + (size_t)(k0 + BK) * N);
        }

        #pragma unroll
        for (int kk = 0; kk < BK; kk++) {
            float a[8], b[8];
            *(float4*)&a[0] = *(const float4*)&As[kk][ty * 8];
            *(float4*)&a[4] = *(const float4*)&As[kk][ty * 8 + 4];
            *(float4*)&b[0] = *(const float4*)&Bs[kk][tx * 8];
            *(float4*)&b[4] = *(const float4*)&Bs[kk][tx * 8 + 4];
            #pragma unroll
            for (int i = 0; i < 8; i++)
                #pragma unroll
                for (int j = 0; j < 8; j++)
                    acc[i][j] += a[i] * b[j];
        }
        __syncthreads();
    }

    #pragma unroll
    for (int i = 0; i < 8; i++) {
        float* Crow = C + (size_t)(m0 + ty * 8 + i) * N + n0 + tx * 8;
        *(float4*)Crow       = make_float4(acc[i][0], acc[i][1], acc[i][2], acc[i][3]);
        *(float4*)(Crow + 4) = make_float4(acc[i][4], acc[i][5], acc[i][6], acc[i][7]);
    }
}

__global__ __launch_bounds__(256)
void qkv_gemm_kernel(const float* __restrict__ x, const float* __restrict__ w)
{
    gemm_body<M_, 3 * C_, C_>(x, w, g_qkv);
}

__global__ __launch_bounds__(256)
void proj_gemm_kernel(const float* __restrict__ w, float* __restrict__ out)
{
    gemm_body<M_, C_, C_>(g_y, w, out);
}

// ---------------------------------------------------------------------------
// Flash attention: one block = 64 queries of one (b, h).
// One thread = one query row. Q and O in registers, K/V tiles in smem
// (broadcast reads), S tile staged in padded smem. Causal tile skipping.
// ---------------------------------------------------------------------------
__global__ __launch_bounds__(64)
void attn_kernel()
{
    __shared__ float Ks[64][DH];
    __shared__ float Vs[64][DH];
    __shared__ float Ss[64][65];   // +1 pad: row-major per-thread access stays conflict-free

    const int r  = threadIdx.x;        // query row within tile
    const int qb = blockIdx.x;         // query tile index
    const int h  = blockIdx.y;
    const int b  = blockIdx.z;
    const int qg = qb * 64 + r;        // global query index

    const float* base = g_qkv + (size_t)b * T_ * 3 * C_;
    const float* qrow = base + (size_t)qg * 3 * C_ + h * DH;

    // Q row in registers, pre-scaled by 1/sqrt(D)
    float q[DH];
    #pragma unroll
    for (int d4 = 0; d4 < DH / 4; d4++) {
        float4 v = *(const float4*)(qrow + d4 * 4);
        q[d4 * 4 + 0] = v.x * 0.125f;
        q[d4 * 4 + 1] = v.y * 0.125f;
        q[d4 * 4 + 2] = v.z * 0.125f;
        q[d4 * 4 + 3] = v.w * 0.125f;
    }

    float m = -1e30f, l = 0.f;
    float o[DH];
    #pragma unroll
    for (int d = 0; d < DH; d++) o[d] = 0.f;

    for (int kt = 0; kt <= qb; kt++) {
        __syncthreads();   // previous tile's compute done before overwrite
        const float* kbase = base + (size_t)(kt * 64) * 3 * C_ + C_ + h * DH;
        const float* vbase = kbase + C_;
        // cooperative, coalesced float4 tile loads
        for (int i = r; i < 64 * DH / 4; i += 64) {
            int row = i >> 4;
            int c4  = i & 15;
            ((float4*)&Ks[row][0])[c4] = ((const float4*)(kbase + (size_t)row * 3 * C_))[c4];
            ((float4*)&Vs[row][0])[c4] = ((const float4*)(vbase + (size_t)row * 3 * C_))[c4];
        }
        __syncthreads();

        // S = Q K^T (per-row), track running max
        float mt = m;
        const bool diag = (kt == qb);
        for (int j = 0; j < 64; j++) {
            float s = 0.f;
            #pragma unroll
            for (int d = 0; d < DH; d++) s += q[d] * Ks[j][d];
            if (diag && (kt * 64 + j) > qg) s = -1e30f;
            Ss[r][j] = s;
            mt = fmaxf(mt, s);
        }

        // online softmax rescale
        float scale = __expf(m - mt);
        m = mt;
        l *= scale;
        #pragma unroll
        for (int d = 0; d < DH; d++) o[d] *= scale;

        // O += P V
        for (int j = 0; j < 64; j++) {
            float p = __expf(Ss[r][j] - m);
            l += p;
            #pragma unroll
            for (int d = 0; d < DH; d++) o[d] += p * Vs[j][d];
        }
    }

    const float inv = 1.f / l;
    float* yrow = g_y + (size_t)((size_t)b * T_ + qg) * C_ + h * DH;
    #pragma unroll
    for (int d4 = 0; d4 < DH / 4; d4++) {
        float4 v;
        v.x = o[d4 * 4 + 0] * inv;
        v.y = o[d4 * 4 + 1] * inv;
        v.z = o[d4 * 4 + 2] * inv;
        v.w = o[d4 * 4 + 3] * inv;
        *(float4*)(yrow + d4 * 4) = v;
    }
}

// ---------------------------------------------------------------------------
extern "C" void kernel_launch(void* const* d_in, const int* in_sizes, int n_in,
                              void* d_out, int out_size)
{
    const float* x      = (const float*)d_in[0];
    const float* w_attn = (const float*)d_in[1];
    const float* w_proj = (const float*)d_in[2];
    float* out = (float*)d_out;

    // 1) QKV projection: [4096,1024] @ [1024,3072] -> g_qkv
    {
        dim3 grid(3 * C_ / 128, M_ / 128);
        qkv_gemm_kernel<<<grid, 256>>>(x, w_attn);
    }
    // 2) causal flash attention -> g_y
    {
        dim3 grid(T_ / 64, H_, B_);
        attn_kernel<<<grid, 64>>>();
    }
    // 3) output projection: [4096,1024] @ [1024,1024] -> out
    {
        dim3 grid(C_ / 128, M_ / 128);
        proj_gemm_kernel<<<grid, 256>>>(w_proj, out);
    }
}

// round 2
// speedup vs baseline: 1.0748x; 1.0748x over previous
#include <cuda_runtime.h>

#define B_  2
#define T_  2048
#define C_  1024
#define H_  16
#define DH  64
#define M_  (B_ * T_)

// Scratch (static device globals — no runtime allocation)
__device__ float g_qkv[(size_t)M_ * 3 * C_];   // [4096, 3072]
__device__ float g_y  [(size_t)M_ * C_];       // [4096, 1024]

// ---------------------------------------------------------------------------
// 128x128x16 register-blocked SGEMM, 256 threads, 8x8 per-thread tile,
// DOUBLE-BUFFERED smem + global->reg prefetch. One __syncthreads per K-tile.
// A [M,K] row-major, B [K,N] row-major, C [M,N] row-major.
// ---------------------------------------------------------------------------
template<int M, int N, int K>
__device__ __forceinline__ void gemm_body(const float* __restrict__ A,
                                          const float* __restrict__ B,
                                          float* __restrict__ C)
{
    constexpr int BM = 128, BN = 128, BK = 16;
    __shared__ float As[2][BK][BM];
    __shared__ float Bs[2][BK][BN];

    const int tid = threadIdx.x;
    const int m0 = blockIdx.y * BM;
    const int n0 = blockIdx.x * BN;

    // A loaders: two rows (ar, ar+64), k-quad ak
    const int ar = tid >> 2;            // 0..63
    const int ak = (tid & 3) * 4;       // 0,4,8,12
    // B loaders: two k-rows (br, br+8), col-quad bn
    const int br = tid >> 5;            // 0..7
    const int bn = (tid & 31) * 4;      // 0..124

    const float* Ap0 = A + (size_t)(m0 + ar)      * K + ak;
    const float* Ap1 = A + (size_t)(m0 + ar + 64) * K + ak;
    const float* Bp0 = B + (size_t)br       * N + n0 + bn;
    const float* Bp1 = B + (size_t)(br + 8) * N + n0 + bn;

    float4 a0 = *(const float4*)Ap0;
    float4 a1 = *(const float4*)Ap1;
    float4 b0 = *(const float4*)Bp0;
    float4 b1 = *(const float4*)Bp1;

    const int tx = tid & 15;
    const int ty = tid >> 4;

    float acc[8][8];
    #pragma unroll
    for (int i = 0; i < 8; i++)
        #pragma unroll
        for (int j = 0; j < 8; j++) acc[i][j] = 0.f;

    // stage 0 store
    As[0][ak + 0][ar] = a0.x;  As[0][ak + 1][ar] = a0.y;
    As[0][ak + 2][ar] = a0.z;  As[0][ak + 3][ar] = a0.w;
    As[0][ak + 0][ar + 64] = a1.x;  As[0][ak + 1][ar + 64] = a1.y;
    As[0][ak + 2][ar + 64] = a1.z;  As[0][ak + 3][ar + 64] = a1.w;
    *(float4*)&Bs[0][br][bn]     = b0;
    *(float4*)&Bs[0][br + 8][bn] = b1;
    __syncthreads();

    int cur = 0;
    for (int k0 = 0; k0 < K; k0 += BK) {
        const bool has_next = (k0 + BK < K);
        if (has_next) {
            a0 = *(const float4*)(Ap0 + k0 + BK);
            a1 = *(const float4*)(Ap1 + k0 + BK);
            b0 = *(const float4*)(Bp0 + (size_t)(k0 + BK) * N);
            b1 = *(const float4*)(Bp1 + (size_t)(k0 + BK) * N);
        }

        #pragma unroll
        for (int kk = 0; kk < BK; kk++) {
            float a[8], b[8];
            *(float4*)&a[0] = *(const float4*)&As[cur][kk][ty * 8];
            *(float4*)&a[4] = *(const float4*)&As[cur][kk][ty * 8 + 4];
            *(float4*)&b[0] = *(const float4*)&Bs[cur][kk][tx * 8];
            *(float4*)&b[4] = *(const float4*)&Bs[cur][kk][tx * 8 + 4];
            #pragma unroll
            for (int i = 0; i < 8; i++)
                #pragma unroll
                for (int j = 0; j < 8; j++)
                    acc[i][j] += a[i] * b[j];
        }

        if (has_next) {
            const int nxt = cur ^ 1;
            As[nxt][ak + 0][ar] = a0.x;  As[nxt][ak + 1][ar] = a0.y;
            As[nxt][ak + 2][ar] = a0.z;  As[nxt][ak + 3][ar] = a0.w;
            As[nxt][ak + 0][ar + 64] = a1.x;  As[nxt][ak + 1][ar + 64] = a1.y;
            As[nxt][ak + 2][ar + 64] = a1.z;  As[nxt][ak + 3][ar + 64] = a1.w;
            *(float4*)&Bs[nxt][br][bn]     = b0;
            *(float4*)&Bs[nxt][br + 8][bn] = b1;
            __syncthreads();
            cur = nxt;
        }
    }

    #pragma unroll
    for (int i = 0; i < 8; i++) {
        float* Crow = C + (size_t)(m0 + ty * 8 + i) * N + n0 + tx * 8;
        *(float4*)Crow       = make_float4(acc[i][0], acc[i][1], acc[i][2], acc[i][3]);
        *(float4*)(Crow + 4) = make_float4(acc[i][4], acc[i][5], acc[i][6], acc[i][7]);
    }
}

__global__ __launch_bounds__(256)
void qkv_gemm_kernel(const float* __restrict__ x, const float* __restrict__ w)
{
    gemm_body<M_, 3 * C_, C_>(x, w, g_qkv);
}

__global__ __launch_bounds__(256)
void proj_gemm_kernel(const float* __restrict__ w, float* __restrict__ out)
{
    gemm_body<M_, C_, C_>(g_y, w, out);
}

// ---------------------------------------------------------------------------
// Flash attention: one block = 64 queries of one (b, h).
// One thread = one query row. Q and O in registers, K/V tiles in smem.
// S loop uses 4 independent accumulators (ILP-4 to break the FMA chain).
// Blocks reversed: heavy (large qb) tiles scheduled first.
// ---------------------------------------------------------------------------
__global__ __launch_bounds__(64)
void attn_kernel()
{
    __shared__ float Ks[64][DH];
    __shared__ float Vs[64][DH];
    __shared__ float Ss[64][65];   // +1 pad

    const int r  = threadIdx.x;                       // query row in tile
    const int qb = (gridDim.x - 1) - blockIdx.x;      // reversed: heavy first
    const int h  = blockIdx.y;
    const int b  = blockIdx.z;
    const int qg = qb * 64 + r;

    const float* base = g_qkv + (size_t)b * T_ * 3 * C_;
    const float* qrow = base + (size_t)qg * 3 * C_ + h * DH;

    float q[DH];
    #pragma unroll
    for (int d4 = 0; d4 < DH / 4; d4++) {
        float4 v = *(const float4*)(qrow + d4 * 4);
        q[d4 * 4 + 0] = v.x * 0.125f;
        q[d4 * 4 + 1] = v.y * 0.125f;
        q[d4 * 4 + 2] = v.z * 0.125f;
        q[d4 * 4 + 3] = v.w * 0.125f;
    }

    float m = -1e30f, l = 0.f;
    float o[DH];
    #pragma unroll
    for (int d = 0; d < DH; d++) o[d] = 0.f;

    for (int kt = 0; kt <= qb; kt++) {
        __syncthreads();
        const float* kbase = base + (size_t)(kt * 64) * 3 * C_ + C_ + h * DH;
        const float* vbase = kbase + C_;
        for (int i = r; i < 64 * DH / 4; i += 64) {
            int row = i >> 4;
            int c4  = i & 15;
            ((float4*)&Ks[row][0])[c4] = ((const float4*)(kbase + (size_t)row * 3 * C_))[c4];
            ((float4*)&Vs[row][0])[c4] = ((const float4*)(vbase + (size_t)row * 3 * C_))[c4];
        }
        __syncthreads();

        // S = Q K^T, 4 keys at a time for ILP
        float mt = m;
        const bool diag = (kt == qb);
        const int kt64 = kt * 64;
        for (int j = 0; j < 64; j += 4) {
            float s0 = 0.f, s1 = 0.f, s2 = 0.f, s3 = 0.f;
            #pragma unroll
            for (int d = 0; d < DH; d++) {
                const float qd = q[d];
                s0 += qd * Ks[j + 0][d];
                s1 += qd * Ks[j + 1][d];
                s2 += qd * Ks[j + 2][d];
                s3 += qd * Ks[j + 3][d];
            }
            if (diag) {
                if (kt64 + j + 0 > qg) s0 = -1e30f;
                if (kt64 + j + 1 > qg) s1 = -1e30f;
                if (kt64 + j + 2 > qg) s2 = -1e30f;
                if (kt64 + j + 3 > qg) s3 = -1e30f;
            }
            Ss[r][j + 0] = s0;  Ss[r][j + 1] = s1;
            Ss[r][j + 2] = s2;  Ss[r][j + 3] = s3;
            mt = fmaxf(mt, fmaxf(fmaxf(s0, s1), fmaxf(s2, s3)));
        }

        // online softmax rescale
        const float scale = __expf(m - mt);
        m = mt;
        l *= scale;
        #pragma unroll
        for (int d = 0; d < DH; d++) o[d] *= scale;

        // O += P V
        for (int j = 0; j < 64; j++) {
            const float p = __expf(Ss[r][j] - m);
            l += p;
            #pragma unroll
            for (int d = 0; d < DH; d++) o[d] += p * Vs[j][d];
        }
    }

    const float inv = 1.f / l;
    float* yrow = g_y + (size_t)((size_t)b * T_ + qg) * C_ + h * DH;
    #pragma unroll
    for (int d4 = 0; d4 < DH / 4; d4++) {
        float4 v;
        v.x = o[d4 * 4 + 0] * inv;
        v.y = o[d4 * 4 + 1] * inv;
        v.z = o[d4 * 4 + 2] * inv;
        v.w = o[d4 * 4 + 3] * inv;
        *(float4*)(yrow + d4 * 4) = v;
    }
}

// ---------------------------------------------------------------------------
extern "C" void kernel_launch(void* const* d_in, const int* in_sizes, int n_in,
                              void* d_out, int out_size)
{
    const float* x      = (const float*)d_in[0];
    const float* w_attn = (const float*)d_in[1];
    const float* w_proj = (const float*)d_in[2];
    float* out = (float*)d_out;

    // 1) QKV projection: [4096,1024] @ [1024,3072] -> g_qkv
    {
        dim3 grid(3 * C_ / 128, M_ / 128);
        qkv_gemm_kernel<<<grid, 256>>>(x, w_attn);
    }
    // 2) causal flash attention -> g_y
    {
        dim3 grid(T_ / 64, H_, B_);
        attn_kernel<<<grid, 64>>>();
    }
    // 3) output projection: [4096,1024] @ [1024,1024] -> out
    {
        dim3 grid(C_ / 128, M_ / 128);
        proj_gemm_kernel<<<grid, 256>>>(w_proj, out);
    }
}

// round 4
// speedup vs baseline: 1.6281x; 1.5148x over previous
#include <cuda_runtime.h>
#include <cuda_bf16.h>
#include <cstdint>

#define B_  2
#define T_  2048
#define C_  1024
#define H_  16
#define DH  64
#define M_  (B_ * T_)
#define KD  1024

// ---------------- scratch (static device globals) ----------------
__device__ float g_qkv[(size_t)M_ * 3 * C_];     // [4096,3072]
__device__ float g_y  [(size_t)M_ * C_];         // [4096,1024]
__device__ __nv_bfloat16 g_xhi[(size_t)M_ * KD];
__device__ __nv_bfloat16 g_xlo[(size_t)M_ * KD];
__device__ __nv_bfloat16 g_wahi[(size_t)3 * C_ * KD];   // W_attn^T [3072,1024]
__device__ __nv_bfloat16 g_walo[(size_t)3 * C_ * KD];
__device__ __nv_bfloat16 g_wphi[(size_t)C_ * KD];       // W_proj^T [1024,1024]
__device__ __nv_bfloat16 g_wplo[(size_t)C_ * KD];
__device__ __nv_bfloat16 g_yhi[(size_t)M_ * KD];
__device__ __nv_bfloat16 g_ylo[(size_t)M_ * KD];

// ---------------- base-ISA PTX helpers (sm_80+, valid on plain sm_103) -----
__device__ __forceinline__ uint32_t smem_u32(const void* p) {
    uint32_t a;
    asm("{ .reg .u64 t; cvta.to.shared.u64 t, %1; cvt.u32.u64 %0, t; }" : "=r"(a) : "l"(p));
    return a;
}
__device__ __forceinline__ void cp16(uint32_t s, const void* g) {
    asm volatile("cp.async.cg.shared.global [%0], [%1], 16;" :: "r"(s), "l"(g));
}
__device__ __forceinline__ void cp_commit() {
    asm volatile("cp.async.commit_group;" ::: "memory");
}
__device__ __forceinline__ void cp_wait1() {
    asm volatile("cp.async.wait_group 1;" ::: "memory");
}
#define LDSM4(R, addr) \
    asm volatile("ldmatrix.sync.aligned.m8n8.x4.shared.b16 {%0,%1,%2,%3}, [%4];" \
                 : "=r"((R)[0]), "=r"((R)[1]), "=r"((R)[2]), "=r"((R)[3]) : "r"(addr))

__device__ __forceinline__ void mma16816(float* c, const uint32_t* a, const uint32_t* b) {
    asm volatile(
        "mma.sync.aligned.m16n8k16.row.col.f32.bf16.bf16.f32 "
        "{%0,%1,%2,%3}, {%4,%5,%6,%7}, {%8,%9}, {%0,%1,%2,%3};"
        : "+f"(c[0]), "+f"(c[1]), "+f"(c[2]), "+f"(c[3])
        : "r"(a[0]), "r"(a[1]), "r"(a[2]), "r"(a[3]), "r"(b[0]), "r"(b[1]));
}

// ---------------- fp32 -> bf16 hi/lo split ----------------
__device__ __forceinline__ void split2(float v, __nv_bfloat16& h, __nv_bfloat16& l) {
    h = __float2bfloat16(v);
    l = __float2bfloat16(v - __bfloat162float(h));
}

__global__ __launch_bounds__(256)
void split_kernel(const float* __restrict__ in,
                  __nv_bfloat16* __restrict__ hi, __nv_bfloat16* __restrict__ lo, int n)
{
    int i = (blockIdx.x * 256 + threadIdx.x) * 4;
    if (i >= n) return;
    float4 v = *(const float4*)(in + i);
    __nv_bfloat16 h0, h1, h2, h3, l0, l1, l2, l3;
    split2(v.x, h0, l0); split2(v.y, h1, l1);
    split2(v.z, h2, l2); split2(v.w, h3, l3);
    *(__nv_bfloat162*)(hi + i)     = __halves2bfloat162(h0, h1);
    *(__nv_bfloat162*)(hi + i + 2) = __halves2bfloat162(h2, h3);
    *(__nv_bfloat162*)(lo + i)     = __halves2bfloat162(l0, l1);
    *(__nv_bfloat162*)(lo + i + 2) = __halves2bfloat162(l2, l3);
}

// transpose + split: W fp32 [Kdim, Ndim] -> hiT/loT bf16 [Ndim, Kdim]
__global__ __launch_bounds__(256)
void splitT_kernel(const float* __restrict__ W,
                   __nv_bfloat16* __restrict__ hiT, __nv_bfloat16* __restrict__ loT,
                   int Kdim, int Ndim)
{
    __shared__ float tile[32][33];
    const int k0 = blockIdx.x * 32, n0 = blockIdx.y * 32;
    const int tx = threadIdx.x, ty = threadIdx.y;   // 32 x 8
    #pragma unroll
    for (int i = 0; i < 32; i += 8)
        tile[ty + i][tx] = W[(size_t)(k0 + ty + i) * Ndim + n0 + tx];
    __syncthreads();
    #pragma unroll
    for (int i = 0; i < 32; i += 8) {
        float v = tile[tx][ty + i];
        __nv_bfloat16 h, l;
        split2(v, h, l);
        size_t o = (size_t)(n0 + ty + i) * Kdim + k0 + tx;
        hiT[o] = h;
        loT[o] = l;
    }
}

// ---------------------------------------------------------------------------
// bf16x3 HMMA GEMM (mma.sync m16n8k16): C[128x128] = (Ahi+Alo)(Bhi+Blo)^T.
// A*,B* bf16 K-major [rows,1024]. BK=64 (128B SW128-swizzled rows),
// 2-stage cp.async pipeline. 8 warps in 2(M) x 4(N), warp tile 64x32.
// ---------------------------------------------------------------------------
#define MAT_BYTES   16384            // 128 rows x 128B
#define STAGE_BYTES (4 * MAT_BYTES)  // Ahi, Alo, Bhi, Blo
#define GEMM_SMEM   (2 * STAGE_BYTES)
#define NSTAGE      (KD / 64)        // 16

template<int NT>
__device__ __forceinline__ void gemm_hmma_body(
    const __nv_bfloat16* __restrict__ Ahi, const __nv_bfloat16* __restrict__ Alo,
    const __nv_bfloat16* __restrict__ Bhi, const __nv_bfloat16* __restrict__ Blo,
    float* __restrict__ Cout)
{
    extern __shared__ __align__(128) char smem_raw[];
    const uint32_t smem = smem_u32(smem_raw);

    const int tid    = threadIdx.x;
    const int lane   = tid & 31;
    const int warp   = tid >> 5;
    const int warp_m = warp & 1;     // 0..1
    const int warp_n = warp >> 1;    // 0..3
    const int m0 = blockIdx.y * 128;
    const int n0 = blockIdx.x * 128;

    const __nv_bfloat16* mats[4] = { Ahi, Alo, Bhi, Blo };
    const int rowbase[2] = { m0, n0 };

    // stage loader: 4 mats x 128 rows x 8 chunks(16B) = 4096 chunks, 16/thread
    auto load_stage = [&](int kofs, uint32_t stage_u32) {
        #pragma unroll
        for (int t = 0; t < 16; t++) {
            const int mat = t >> 2;                      // compile-time
            const int rem = ((t & 3) << 8) + tid;        // 0..1023
            const int row = rem >> 3;
            const int ch  = tid & 7;
            const __nv_bfloat16* g = mats[mat]
                + (size_t)(rowbase[mat >> 1] + row) * KD + kofs + ch * 8;
            uint32_t s = stage_u32 + mat * MAT_BYTES + row * 128
                       + ((ch ^ (row & 7)) << 4);
            cp16(s, g);
        }
    };

    float acc[4][4][4];
    #pragma unroll
    for (int i = 0; i < 4; i++)
        #pragma unroll
        for (int j = 0; j < 4; j++)
            #pragma unroll
            for (int k = 0; k < 4; k++) acc[i][j][k] = 0.f;

    // prologue: stages 0,1
    load_stage(0, smem);
    cp_commit();
    load_stage(64, smem + STAGE_BYTES);
    cp_commit();
    cp_wait1();
    __syncthreads();

    // precompute per-lane fragment rows
    const int arow = warp_m * 64 + (lane & 15);    // + mt*16
    const int ah_  = lane >> 4;                    // k-half for A
    const int brow = warp_n * 32 + ((lane >> 4) << 3) + (lane & 7);  // + np*16
    const int bkh  = (lane >> 3) & 1;

    for (int ks = 0; ks < NSTAGE; ks++) {
        const uint32_t sb = smem + (ks & 1) * STAGE_BYTES;

        #pragma unroll
        for (int kk = 0; kk < 4; kk++) {
            uint32_t ahf[4][4], alf[4][4], bhf[4][2], blf[4][2];
            #pragma unroll
            for (int mt = 0; mt < 4; mt++) {
                const int r = arow + mt * 16;
                const uint32_t off = r * 128 + ((((kk << 1) | ah_) ^ (r & 7)) << 4);
                LDSM4(ahf[mt], sb + off);
                LDSM4(alf[mt], sb + MAT_BYTES + off);
            }
            #pragma unroll
            for (int np = 0; np < 2; np++) {
                const int r = brow + np * 16;
                const uint32_t off = r * 128 + ((((kk << 1) | bkh) ^ (r & 7)) << 4);
                uint32_t q[4];
                LDSM4(q, sb + 2 * MAT_BYTES + off);
                bhf[np * 2 + 0][0] = q[0];  bhf[np * 2 + 0][1] = q[1];
                bhf[np * 2 + 1][0] = q[2];  bhf[np * 2 + 1][1] = q[3];
                LDSM4(q, sb + 3 * MAT_BYTES + off);
                blf[np * 2 + 0][0] = q[0];  blf[np * 2 + 0][1] = q[1];
                blf[np * 2 + 1][0] = q[2];  blf[np * 2 + 1][1] = q[3];
            }
            #pragma unroll
            for (int mt = 0; mt < 4; mt++)
                #pragma unroll
                for (int nt = 0; nt < 4; nt++) {
                    mma16816(acc[mt][nt], ahf[mt], bhf[nt]);
                    mma16816(acc[mt][nt], ahf[mt], blf[nt]);
                    mma16816(acc[mt][nt], alf[mt], bhf[nt]);
                }
        }

        __syncthreads();                 // all warps done reading this buffer
        if (ks + 2 < NSTAGE)
            load_stage((ks + 2) * 64, sb);
        cp_commit();                     // (possibly empty) keeps group count uniform
        cp_wait1();                      // stage ks+1 resident
        __syncthreads();
    }

    // epilogue: registers -> global
    const int g  = lane >> 2;
    const int tg = lane & 3;
    #pragma unroll
    for (int mt = 0; mt < 4; mt++) {
        #pragma unroll
        for (int nt = 0; nt < 4; nt++) {
            const int row = m0 + warp_m * 64 + mt * 16 + g;
            const int col = n0 + warp_n * 32 + nt * 8 + tg * 2;
            *(float2*)(Cout + (size_t)row * NT + col) =
                make_float2(acc[mt][nt][0], acc[mt][nt][1]);
            *(float2*)(Cout + (size_t)(row + 8) * NT + col) =
                make_float2(acc[mt][nt][2], acc[mt][nt][3]);
        }
    }
}

__global__ __launch_bounds__(256, 1)
void qkv_gemm_tc() { gemm_hmma_body<3 * C_>(g_xhi, g_xlo, g_wahi, g_walo, g_qkv); }

__global__ __launch_bounds__(256, 1)
void proj_gemm_tc(float* __restrict__ out) { gemm_hmma_body<C_>(g_yhi, g_ylo, g_wphi, g_wplo, out); }

// ---------------------------------------------------------------------------
// Flash attention (round-2 winner, unchanged): 64 queries/block, ILP-4 score
// loop, reversed scheduling.
// ---------------------------------------------------------------------------
__global__ __launch_bounds__(64)
void attn_kernel()
{
    __shared__ float Ks[64][DH];
    __shared__ float Vs[64][DH];
    __shared__ float Ss[64][65];

    const int r  = threadIdx.x;
    const int qb = (gridDim.x - 1) - blockIdx.x;
    const int h  = blockIdx.y;
    const int b  = blockIdx.z;
    const int qg = qb * 64 + r;

    const float* base = g_qkv + (size_t)b * T_ * 3 * C_;
    const float* qrow = base + (size_t)qg * 3 * C_ + h * DH;

    float q[DH];
    #pragma unroll
    for (int d4 = 0; d4 < DH / 4; d4++) {
        float4 v = *(const float4*)(qrow + d4 * 4);
        q[d4 * 4 + 0] = v.x * 0.125f;
        q[d4 * 4 + 1] = v.y * 0.125f;
        q[d4 * 4 + 2] = v.z * 0.125f;
        q[d4 * 4 + 3] = v.w * 0.125f;
    }

    float m = -1e30f, l = 0.f;
    float o[DH];
    #pragma unroll
    for (int d = 0; d < DH; d++) o[d] = 0.f;

    for (int kt = 0; kt <= qb; kt++) {
        __syncthreads();
        const float* kbase = base + (size_t)(kt * 64) * 3 * C_ + C_ + h * DH;
        const float* vbase = kbase + C_;
        for (int i = r; i < 64 * DH / 4; i += 64) {
            int row = i >> 4;
            int c4  = i & 15;
            ((float4*)&Ks[row][0])[c4] = ((const float4*)(kbase + (size_t)row * 3 * C_))[c4];
            ((float4*)&Vs[row][0])[c4] = ((const float4*)(vbase + (size_t)row * 3 * C_))[c4];
        }
        __syncthreads();

        float mt = m;
        const bool diag = (kt == qb);
        const int kt64 = kt * 64;
        for (int j = 0; j < 64; j += 4) {
            float s0 = 0.f, s1 = 0.f, s2 = 0.f, s3 = 0.f;
            #pragma unroll
            for (int d = 0; d < DH; d++) {
                const float qd = q[d];
                s0 += qd * Ks[j + 0][d];
                s1 += qd * Ks[j + 1][d];
                s2 += qd * Ks[j + 2][d];
                s3 += qd * Ks[j + 3][d];
            }
            if (diag) {
                if (kt64 + j + 0 > qg) s0 = -1e30f;
                if (kt64 + j + 1 > qg) s1 = -1e30f;
                if (kt64 + j + 2 > qg) s2 = -1e30f;
                if (kt64 + j + 3 > qg) s3 = -1e30f;
            }
            Ss[r][j + 0] = s0;  Ss[r][j + 1] = s1;
            Ss[r][j + 2] = s2;  Ss[r][j + 3] = s3;
            mt = fmaxf(mt, fmaxf(fmaxf(s0, s1), fmaxf(s2, s3)));
        }

        const float scale = __expf(m - mt);
        m = mt;
        l *= scale;
        #pragma unroll
        for (int d = 0; d < DH; d++) o[d] *= scale;

        for (int j = 0; j < 64; j++) {
            const float p = __expf(Ss[r][j] - m);
            l += p;
            #pragma unroll
            for (int d = 0; d < DH; d++) o[d] += p * Vs[j][d];
        }
    }

    const float inv = 1.f / l;
    float* yrow = g_y + (size_t)((size_t)b * T_ + qg) * C_ + h * DH;
    #pragma unroll
    for (int d4 = 0; d4 < DH / 4; d4++) {
        float4 v;
        v.x = o[d4 * 4 + 0] * inv;
        v.y = o[d4 * 4 + 1] * inv;
        v.z = o[d4 * 4 + 2] * inv;
        v.w = o[d4 * 4 + 3] * inv;
        *(float4*)(yrow + d4 * 4) = v;
    }
}

// ---------------------------------------------------------------------------
extern "C" void kernel_launch(void* const* d_in, const int* in_sizes, int n_in,
                              void* d_out, int out_size)
{
    const float* x      = (const float*)d_in[0];
    const float* w_attn = (const float*)d_in[1];
    const float* w_proj = (const float*)d_in[2];
    float* out = (float*)d_out;

    static bool attr_done = false;
    if (!attr_done) {
        cudaFuncSetAttribute(qkv_gemm_tc,  cudaFuncAttributeMaxDynamicSharedMemorySize, GEMM_SMEM);
        cudaFuncSetAttribute(proj_gemm_tc, cudaFuncAttributeMaxDynamicSharedMemorySize, GEMM_SMEM);
        attr_done = true;
    }

    __nv_bfloat16 *xhi, *xlo, *wahi, *walo, *wphi, *wplo, *yhi, *ylo;
    float* gy;
    cudaGetSymbolAddress((void**)&xhi,  g_xhi);
    cudaGetSymbolAddress((void**)&xlo,  g_xlo);
    cudaGetSymbolAddress((void**)&wahi, g_wahi);
    cudaGetSymbolAddress((void**)&walo, g_walo);
    cudaGetSymbolAddress((void**)&wphi, g_wphi);
    cudaGetSymbolAddress((void**)&wplo, g_wplo);
    cudaGetSymbolAddress((void**)&yhi,  g_yhi);
    cudaGetSymbolAddress((void**)&ylo,  g_ylo);
    cudaGetSymbolAddress((void**)&gy,   g_y);

    // 1) split x -> bf16 hi/lo
    split_kernel<<<(M_ * KD) / 1024, 256>>>(x, xhi, xlo, M_ * KD);
    // 2) transpose+split weights
    {
        dim3 grid(KD / 32, (3 * C_) / 32);
        splitT_kernel<<<grid, dim3(32, 8)>>>(w_attn, wahi, walo, KD, 3 * C_);
    }
    {
        dim3 grid(KD / 32, C_ / 32);
        splitT_kernel<<<grid, dim3(32, 8)>>>(w_proj, wphi, wplo, KD, C_);
    }
    // 3) QKV GEMM (HMMA bf16x3): [4096,1024] x [1024,3072] -> g_qkv
    {
        dim3 grid((3 * C_) / 128, M_ / 128);
        qkv_gemm_tc<<<grid, 256, GEMM_SMEM>>>();
    }
    // 4) causal flash attention -> g_y
    {
        dim3 grid(T_ / 64, H_, B_);
        attn_kernel<<<grid, 64>>>();
    }
    // 5) split y -> bf16 hi/lo
    split_kernel<<<(M_ * KD) / 1024, 256>>>(gy, yhi, ylo, M_ * KD);
    // 6) proj GEMM (HMMA bf16x3): [4096,1024] x [1024,1024] -> out
    {
        dim3 grid(C_ / 128, M_ / 128);
        proj_gemm_tc<<<grid, 256, GEMM_SMEM>>>(out);
    }
}

// round 5
// speedup vs baseline: 3.7135x; 2.2809x over previous
#include <cuda_runtime.h>
#include <cuda_bf16.h>
#include <cstdint>

#define B_  2
#define T_  2048
#define C_  1024
#define H_  16
#define DH  64
#define M_  (B_ * T_)
#define KD  1024

// ---------------- scratch (static device globals) ----------------
__device__ float g_qkv[(size_t)M_ * 3 * C_];     // [4096,3072]
__device__ __nv_bfloat16 g_xhi[(size_t)M_ * KD];
__device__ __nv_bfloat16 g_xlo[(size_t)M_ * KD];
__device__ __nv_bfloat16 g_wahi[(size_t)3 * C_ * KD];   // W_attn^T [3072,1024]
__device__ __nv_bfloat16 g_walo[(size_t)3 * C_ * KD];
__device__ __nv_bfloat16 g_wphi[(size_t)C_ * KD];       // W_proj^T [1024,1024]
__device__ __nv_bfloat16 g_wplo[(size_t)C_ * KD];
__device__ __nv_bfloat16 g_yhi[(size_t)M_ * KD];        // attention out (hi)
__device__ __nv_bfloat16 g_ylo[(size_t)M_ * KD];        // attention out (lo)
// head-major attention operands
__device__ __nv_bfloat16 g_qh[(size_t)B_ * H_ * T_ * DH];
__device__ __nv_bfloat16 g_ql[(size_t)B_ * H_ * T_ * DH];
__device__ __nv_bfloat16 g_kh[(size_t)B_ * H_ * T_ * DH];
__device__ __nv_bfloat16 g_kl[(size_t)B_ * H_ * T_ * DH];
__device__ __nv_bfloat16 g_vth[(size_t)B_ * H_ * DH * T_];   // transposed [bh][d][t]
__device__ __nv_bfloat16 g_vtl[(size_t)B_ * H_ * DH * T_];

// ---------------- base-ISA PTX helpers (sm_80+) ----------------
__device__ __forceinline__ uint32_t smem_u32(const void* p) {
    uint32_t a;
    asm("{ .reg .u64 t; cvta.to.shared.u64 t, %1; cvt.u32.u64 %0, t; }" : "=r"(a) : "l"(p));
    return a;
}
__device__ __forceinline__ void cp16(uint32_t s, const void* g) {
    asm volatile("cp.async.cg.shared.global [%0], [%1], 16;" :: "r"(s), "l"(g));
}
__device__ __forceinline__ void cp_commit() {
    asm volatile("cp.async.commit_group;" ::: "memory");
}
__device__ __forceinline__ void cp_wait1() {
    asm volatile("cp.async.wait_group 1;" ::: "memory");
}
#define LDSM4(R, addr) \
    asm volatile("ldmatrix.sync.aligned.m8n8.x4.shared.b16 {%0,%1,%2,%3}, [%4];" \
                 : "=r"((R)[0]), "=r"((R)[1]), "=r"((R)[2]), "=r"((R)[3]) : "r"(addr))

__device__ __forceinline__ void mma16816(float* c, const uint32_t* a, const uint32_t* b) {
    asm volatile(
        "mma.sync.aligned.m16n8k16.row.col.f32.bf16.bf16.f32 "
        "{%0,%1,%2,%3}, {%4,%5,%6,%7}, {%8,%9}, {%0,%1,%2,%3};"
        : "+f"(c[0]), "+f"(c[1]), "+f"(c[2]), "+f"(c[3])
        : "r"(a[0]), "r"(a[1]), "r"(a[2]), "r"(a[3]), "r"(b[0]), "r"(b[1]));
}
// pack two fp32 -> bf16x2 reg, lo in low half
__device__ __forceinline__ uint32_t pack_bf16x2(float lo, float hi) {
    uint32_t d;
    asm("cvt.rn.bf16x2.f32 %0, %1, %2;" : "=r"(d) : "f"(hi), "f"(lo));
    return d;
}

// ---------------- fp32 -> bf16 hi/lo split ----------------
__device__ __forceinline__ void split2(float v, __nv_bfloat16& h, __nv_bfloat16& l) {
    h = __float2bfloat16(v);
    l = __float2bfloat16(v - __bfloat162float(h));
}

__global__ __launch_bounds__(256)
void split_kernel(const float* __restrict__ in,
                  __nv_bfloat16* __restrict__ hi, __nv_bfloat16* __restrict__ lo, int n)
{
    int i = (blockIdx.x * 256 + threadIdx.x) * 4;
    if (i >= n) return;
    float4 v = *(const float4*)(in + i);
    __nv_bfloat16 h0, h1, h2, h3, l0, l1, l2, l3;
    split2(v.x, h0, l0); split2(v.y, h1, l1);
    split2(v.z, h2, l2); split2(v.w, h3, l3);
    *(__nv_bfloat162*)(hi + i)     = __halves2bfloat162(h0, h1);
    *(__nv_bfloat162*)(hi + i + 2) = __halves2bfloat162(h2, h3);
    *(__nv_bfloat162*)(lo + i)     = __halves2bfloat162(l0, l1);
    *(__nv_bfloat162*)(lo + i + 2) = __halves2bfloat162(l2, l3);
}

__global__ __launch_bounds__(256)
void splitT_kernel(const float* __restrict__ W,
                   __nv_bfloat16* __restrict__ hiT, __nv_bfloat16* __restrict__ loT,
                   int Kdim, int Ndim)
{
    __shared__ float tile[32][33];
    const int k0 = blockIdx.x * 32, n0 = blockIdx.y * 32;
    const int tx = threadIdx.x, ty = threadIdx.y;   // 32 x 8
    #pragma unroll
    for (int i = 0; i < 32; i += 8)
        tile[ty + i][tx] = W[(size_t)(k0 + ty + i) * Ndim + n0 + tx];
    __syncthreads();
    #pragma unroll
    for (int i = 0; i < 32; i += 8) {
        float v = tile[tx][ty + i];
        __nv_bfloat16 h, l;
        split2(v, h, l);
        size_t o = (size_t)(n0 + ty + i) * Kdim + k0 + tx;
        hiT[o] = h;
        loT[o] = l;
    }
}

// repack Q,K halves of g_qkv into head-major bf16 hi/lo (Q pre-scaled by 0.125)
__global__ __launch_bounds__(256)
void repack_qk_kernel()
{
    const int i4 = blockIdx.x * 256 + threadIdx.x;   // over 4096*2048/4
    const int r = i4 >> 9;
    const int c = (i4 & 511) * 4;
    float4 v = *(const float4*)(g_qkv + (size_t)r * 3072 + c);
    const int b = r >> 11, t = r & 2047;
    const int hh = (c & 1023) >> 6, d = c & 63;
    const size_t dst = ((size_t)(b * H_ + hh) * T_ + t) * DH + d;
    const bool isQ = (c < 1024);
    const float sc = isQ ? 0.125f : 1.f;
    __nv_bfloat16 h0, h1, h2, h3, l0, l1, l2, l3;
    split2(v.x * sc, h0, l0); split2(v.y * sc, h1, l1);
    split2(v.z * sc, h2, l2); split2(v.w * sc, h3, l3);
    __nv_bfloat16* hi = isQ ? g_qh : g_kh;
    __nv_bfloat16* lo = isQ ? g_ql : g_kl;
    *(__nv_bfloat162*)(hi + dst)     = __halves2bfloat162(h0, h1);
    *(__nv_bfloat162*)(hi + dst + 2) = __halves2bfloat162(h2, h3);
    *(__nv_bfloat162*)(lo + dst)     = __halves2bfloat162(l0, l1);
    *(__nv_bfloat162*)(lo + dst + 2) = __halves2bfloat162(l2, l3);
}

// repack V half of g_qkv transposed: vt[bh][d][t]
__global__ __launch_bounds__(256)
void repack_vt_kernel()
{
    __shared__ float tile[32][33];
    const int bh = blockIdx.z;
    const int b = bh >> 4, hh = bh & 15;
    const int t0 = blockIdx.x * 32, d0 = blockIdx.y * 32;
    const int tx = threadIdx.x, ty = threadIdx.y;   // 32 x 8
    #pragma unroll
    for (int i = 0; i < 32; i += 8)
        tile[ty + i][tx] = g_qkv[(size_t)(b * T_ + t0 + ty + i) * 3072 + 2048 + hh * 64 + d0 + tx];
    __syncthreads();
    #pragma unroll
    for (int i = 0; i < 32; i += 8) {
        float v = tile[tx][ty + i];
        __nv_bfloat16 h, l;
        split2(v, h, l);
        size_t o = ((size_t)bh * DH + d0 + ty + i) * T_ + t0 + tx;
        g_vth[o] = h;
        g_vtl[o] = l;
    }
}

// ---------------------------------------------------------------------------
// bf16x3 HMMA GEMM (unchanged from round-4 winner)
// ---------------------------------------------------------------------------
#define MAT_BYTES   16384
#define STAGE_BYTES (4 * MAT_BYTES)
#define GEMM_SMEM   (2 * STAGE_BYTES)
#define NSTAGE      (KD / 64)

template<int NT>
__device__ __forceinline__ void gemm_hmma_body(
    const __nv_bfloat16* __restrict__ Ahi, const __nv_bfloat16* __restrict__ Alo,
    const __nv_bfloat16* __restrict__ Bhi, const __nv_bfloat16* __restrict__ Blo,
    float* __restrict__ Cout)
{
    extern __shared__ __align__(128) char smem_raw[];
    const uint32_t smem = smem_u32(smem_raw);

    const int tid    = threadIdx.x;
    const int lane   = tid & 31;
    const int warp   = tid >> 5;
    const int warp_m = warp & 1;
    const int warp_n = warp >> 1;
    const int m0 = blockIdx.y * 128;
    const int n0 = blockIdx.x * 128;

    const __nv_bfloat16* mats[4] = { Ahi, Alo, Bhi, Blo };
    const int rowbase[2] = { m0, n0 };

    auto load_stage = [&](int kofs, uint32_t stage_u32) {
        #pragma unroll
        for (int t = 0; t < 16; t++) {
            const int mat = t >> 2;
            const int rem = ((t & 3) << 8) + tid;
            const int row = rem >> 3;
            const int ch  = tid & 7;
            const __nv_bfloat16* g = mats[mat]
                + (size_t)(rowbase[mat >> 1] + row) * KD + kofs + ch * 8;
            uint32_t s = stage_u32 + mat * MAT_BYTES + row * 128
                       + ((ch ^ (row & 7)) << 4);
            cp16(s, g);
        }
    };

    float acc[4][4][4];
    #pragma unroll
    for (int i = 0; i < 4; i++)
        #pragma unroll
        for (int j = 0; j < 4; j++)
            #pragma unroll
            for (int k = 0; k < 4; k++) acc[i][j][k] = 0.f;

    load_stage(0, smem);
    cp_commit();
    load_stage(64, smem + STAGE_BYTES);
    cp_commit();
    cp_wait1();
    __syncthreads();

    const int arow = warp_m * 64 + (lane & 15);
    const int ah_  = lane >> 4;
    const int brow = warp_n * 32 + ((lane >> 4) << 3) + (lane & 7);
    const int bkh  = (lane >> 3) & 1;

    for (int ks = 0; ks < NSTAGE; ks++) {
        const uint32_t sb = smem + (ks & 1) * STAGE_BYTES;

        #pragma unroll
        for (int kk = 0; kk < 4; kk++) {
            uint32_t ahf[4][4], alf[4][4], bhf[4][2], blf[4][2];
            #pragma unroll
            for (int mt = 0; mt < 4; mt++) {
                const int r = arow + mt * 16;
                const uint32_t off = r * 128 + ((((kk << 1) | ah_) ^ (r & 7)) << 4);
                LDSM4(ahf[mt], sb + off);
                LDSM4(alf[mt], sb + MAT_BYTES + off);
            }
            #pragma unroll
            for (int np = 0; np < 2; np++) {
                const int r = brow + np * 16;
                const uint32_t off = r * 128 + ((((kk << 1) | bkh) ^ (r & 7)) << 4);
                uint32_t q[4];
                LDSM4(q, sb + 2 * MAT_BYTES + off);
                bhf[np * 2 + 0][0] = q[0];  bhf[np * 2 + 0][1] = q[1];
                bhf[np * 2 + 1][0] = q[2];  bhf[np * 2 + 1][1] = q[3];
                LDSM4(q, sb + 3 * MAT_BYTES + off);
                blf[np * 2 + 0][0] = q[0];  blf[np * 2 + 0][1] = q[1];
                blf[np * 2 + 1][0] = q[2];  blf[np * 2 + 1][1] = q[3];
            }
            #pragma unroll
            for (int mt = 0; mt < 4; mt++)
                #pragma unroll
                for (int nt = 0; nt < 4; nt++) {
                    mma16816(acc[mt][nt], ahf[mt], bhf[nt]);
                    mma16816(acc[mt][nt], ahf[mt], blf[nt]);
                    mma16816(acc[mt][nt], alf[mt], bhf[nt]);
                }
        }

        __syncthreads();
        if (ks + 2 < NSTAGE)
            load_stage((ks + 2) * 64, sb);
        cp_commit();
        cp_wait1();
        __syncthreads();
    }

    const int g  = lane >> 2;
    const int tg = lane & 3;
    #pragma unroll
    for (int mt = 0; mt < 4; mt++) {
        #pragma unroll
        for (int nt = 0; nt < 4; nt++) {
            const int row = m0 + warp_m * 64 + mt * 16 + g;
            const int col = n0 + warp_n * 32 + nt * 8 + tg * 2;
            *(float2*)(Cout + (size_t)row * NT + col) =
                make_float2(acc[mt][nt][0], acc[mt][nt][1]);
            *(float2*)(Cout + (size_t)(row + 8) * NT + col) =
                make_float2(acc[mt][nt][2], acc[mt][nt][3]);
        }
    }
}

__global__ __launch_bounds__(256, 1)
void qkv_gemm_tc() { gemm_hmma_body<3 * C_>(g_xhi, g_xlo, g_wahi, g_walo, g_qkv); }

__global__ __launch_bounds__(256, 1)
void proj_gemm_tc(float* __restrict__ out) { gemm_hmma_body<C_>(g_yhi, g_ylo, g_wphi, g_wplo, out); }

// ---------------------------------------------------------------------------
// HMMA flash attention: CTA = 128 queries x one (b,h). 4 warps (32 q-rows ea).
// K tile = 64 keys. bf16x3 for QK^T and PV. Online softmax in registers.
// smem: Q hi/lo (32KB, persistent) + 2 stages x (Khi,Klo,Vthi,Vtlo = 32KB).
// ---------------------------------------------------------------------------
#define ATT_SMEM (32768 + 2 * 32768)

__global__ __launch_bounds__(128, 1)
void attn_hmma_kernel()
{
    extern __shared__ __align__(128) char smem_raw[];
    const uint32_t smem = smem_u32(smem_raw);
    const uint32_t qsm  = smem;            // Qhi 16KB, Qlo 16KB
    const uint32_t st0  = smem + 32768;    // stages

    const int tid  = threadIdx.x;
    const int lane = tid & 31;
    const int warp = tid >> 5;
    const int qt   = (gridDim.x - 1) - blockIdx.x;   // heavy first
    const int bh   = blockIdx.z * H_ + blockIdx.y;
    const size_t qkb = (size_t)bh * T_ * DH;
    const size_t vb  = (size_t)bh * DH * T_;
    const int nkt = 2 * (qt + 1);

    // Q tile load (once)
    {
        const __nv_bfloat16* s0 = g_qh + qkb + (size_t)qt * 128 * DH;
        const __nv_bfloat16* s1 = g_ql + qkb + (size_t)qt * 128 * DH;
        #pragma unroll
        for (int t = 0; t < 16; t++) {
            const int rem = ((t & 7) << 7) + tid;   // 0..1023
            const int row = rem >> 3, ch = rem & 7;
            const __nv_bfloat16* g = ((t >> 3) ? s1 : s0) + (size_t)row * DH + ch * 8;
            cp16(qsm + (t >> 3) * 16384 + row * 128 + ((ch ^ (row & 7)) << 4), g);
        }
    }
    auto load_kv = [&](int kt, uint32_t stage) {
        #pragma unroll
        for (int t = 0; t < 16; t++) {
            const int mat = t >> 2;
            const int rem = ((t & 3) << 7) + tid;   // 0..511
            const int row = rem >> 3, ch = rem & 7;
            const __nv_bfloat16* g;
            if (mat == 0)      g = g_kh  + qkb + (size_t)(kt * 64 + row) * DH + ch * 8;
            else if (mat == 1) g = g_kl  + qkb + (size_t)(kt * 64 + row) * DH + ch * 8;
            else if (mat == 2) g = g_vth + vb  + (size_t)row * T_ + kt * 64 + ch * 8;
            else               g = g_vtl + vb  + (size_t)row * T_ + kt * 64 + ch * 8;
            cp16(stage + mat * 8192 + row * 128 + ((ch ^ (row & 7)) << 4), g);
        }
    };

    load_kv(0, st0);
    cp_commit();
    if (nkt > 1) load_kv(1, st0 + 32768);
    cp_commit();
    cp_wait1();
    __syncthreads();

    const int g   = lane >> 2;
    const int c2  = (lane & 3) * 2;
    const int q0w = qt * 128 + warp * 32;
    const int bkh = (lane >> 3) & 1;
    const int ah_ = lane >> 4;
    const int brow_base = ((lane >> 4) << 3) + (lane & 7);

    float O[2][8][4];
    #pragma unroll
    for (int mt = 0; mt < 2; mt++)
        #pragma unroll
        for (int nt = 0; nt < 8; nt++)
            #pragma unroll
            for (int i = 0; i < 4; i++) O[mt][nt][i] = 0.f;
    float mrun[2][2] = {{-1e30f, -1e30f}, {-1e30f, -1e30f}};
    float lrun[2][2] = {{0.f, 0.f}, {0.f, 0.f}};

    for (int kt = 0; kt < nkt; kt++) {
        const uint32_t sb = st0 + (kt & 1) * 32768;

        float sacc[2][8][4];
        #pragma unroll
        for (int mt = 0; mt < 2; mt++)
            #pragma unroll
            for (int nt = 0; nt < 8; nt++)
                #pragma unroll
                for (int i = 0; i < 4; i++) sacc[mt][nt][i] = 0.f;

        // ---- S = Q K^T (bf16x3) ----
        #pragma unroll
        for (int kk = 0; kk < 4; kk++) {
            uint32_t qhf[2][4], qlf[2][4];
            #pragma unroll
            for (int mt = 0; mt < 2; mt++) {
                const int r = warp * 32 + mt * 16 + (lane & 15);
                const uint32_t off = r * 128 + ((((kk << 1) | ah_) ^ (r & 7)) << 4);
                LDSM4(qhf[mt], qsm + off);
                LDSM4(qlf[mt], qsm + 16384 + off);
            }
            uint32_t khf[8][2], klf[8][2];
            #pragma unroll
            for (int np = 0; np < 4; np++) {
                const int r = np * 16 + brow_base;
                const uint32_t off = r * 128 + ((((kk << 1) | bkh) ^ (r & 7)) << 4);
                uint32_t q4[4];
                LDSM4(q4, sb + off);
                khf[np * 2 + 0][0] = q4[0];  khf[np * 2 + 0][1] = q4[1];
                khf[np * 2 + 1][0] = q4[2];  khf[np * 2 + 1][1] = q4[3];
                LDSM4(q4, sb + 8192 + off);
                klf[np * 2 + 0][0] = q4[0];  klf[np * 2 + 0][1] = q4[1];
                klf[np * 2 + 1][0] = q4[2];  klf[np * 2 + 1][1] = q4[3];
            }
            #pragma unroll
            for (int mt = 0; mt < 2; mt++)
                #pragma unroll
                for (int nt = 0; nt < 8; nt++) {
                    mma16816(sacc[mt][nt], qhf[mt], khf[nt]);
                    mma16816(sacc[mt][nt], qhf[mt], klf[nt]);
                    mma16816(sacc[mt][nt], qlf[mt], khf[nt]);
                }
        }

        // ---- causal mask (only tiles near the diagonal) ----
        if (kt >= 2 * qt) {
            const int kt64 = kt * 64;
            #pragma unroll
            for (int mt = 0; mt < 2; mt++) {
                const int qr0 = q0w + mt * 16 + g;
                #pragma unroll
                for (int nt = 0; nt < 8; nt++) {
                    const int kc = kt64 + nt * 8 + c2;
                    if (kc > qr0)         sacc[mt][nt][0] = -1e30f;
                    if (kc + 1 > qr0)     sacc[mt][nt][1] = -1e30f;
                    if (kc > qr0 + 8)     sacc[mt][nt][2] = -1e30f;
                    if (kc + 1 > qr0 + 8) sacc[mt][nt][3] = -1e30f;
                }
            }
        }

        // ---- online softmax ----
        float alpha[2][2];
        #pragma unroll
        for (int mt = 0; mt < 2; mt++) {
            float h0 = -1e30f, h1 = -1e30f;
            #pragma unroll
            for (int nt = 0; nt < 8; nt++) {
                h0 = fmaxf(h0, fmaxf(sacc[mt][nt][0], sacc[mt][nt][1]));
                h1 = fmaxf(h1, fmaxf(sacc[mt][nt][2], sacc[mt][nt][3]));
            }
            h0 = fmaxf(h0, __shfl_xor_sync(0xffffffffu, h0, 1));
            h0 = fmaxf(h0, __shfl_xor_sync(0xffffffffu, h0, 2));
            h1 = fmaxf(h1, __shfl_xor_sync(0xffffffffu, h1, 1));
            h1 = fmaxf(h1, __shfl_xor_sync(0xffffffffu, h1, 2));
            const float m0 = fmaxf(mrun[mt][0], h0);
            const float m1 = fmaxf(mrun[mt][1], h1);
            alpha[mt][0] = __expf(mrun[mt][0] - m0);
            alpha[mt][1] = __expf(mrun[mt][1] - m1);
            mrun[mt][0] = m0;  mrun[mt][1] = m1;

            float s0 = 0.f, s1 = 0.f;
            #pragma unroll
            for (int nt = 0; nt < 8; nt++) {
                float p0 = __expf(sacc[mt][nt][0] - m0);
                float p1 = __expf(sacc[mt][nt][1] - m0);
                float p2 = __expf(sacc[mt][nt][2] - m1);
                float p3 = __expf(sacc[mt][nt][3] - m1);
                sacc[mt][nt][0] = p0;  sacc[mt][nt][1] = p1;
                sacc[mt][nt][2] = p2;  sacc[mt][nt][3] = p3;
                s0 += p0 + p1;
                s1 += p2 + p3;
            }
            s0 += __shfl_xor_sync(0xffffffffu, s0, 1);
            s0 += __shfl_xor_sync(0xffffffffu, s0, 2);
            s1 += __shfl_xor_sync(0xffffffffu, s1, 1);
            s1 += __shfl_xor_sync(0xffffffffu, s1, 2);
            lrun[mt][0] = lrun[mt][0] * alpha[mt][0] + s0;
            lrun[mt][1] = lrun[mt][1] * alpha[mt][1] + s1;

            #pragma unroll
            for (int nt = 0; nt < 8; nt++) {
                O[mt][nt][0] *= alpha[mt][0];
                O[mt][nt][1] *= alpha[mt][0];
                O[mt][nt][2] *= alpha[mt][1];
                O[mt][nt][3] *= alpha[mt][1];
            }
        }

        // ---- O += P V (bf16x3, P hi/lo built in registers) ----
        #pragma unroll
        for (int kc = 0; kc < 4; kc++) {
            uint32_t ph[2][4], pl[2][4];
            #pragma unroll
            for (int mt = 0; mt < 2; mt++) {
                #pragma unroll
                for (int half = 0; half < 2; half++) {   // tile 2kc, 2kc+1
                    const int nt = 2 * kc + half;
                    float p0 = sacc[mt][nt][0], p1 = sacc[mt][nt][1];
                    float p2 = sacc[mt][nt][2], p3 = sacc[mt][nt][3];
                    float h0 = __bfloat162float(__float2bfloat16(p0));
                    float h1 = __bfloat162float(__float2bfloat16(p1));
                    float h2 = __bfloat162float(__float2bfloat16(p2));
                    float h3 = __bfloat162float(__float2bfloat16(p3));
                    ph[mt][half * 2 + 0] = pack_bf16x2(h0, h1);
                    ph[mt][half * 2 + 1] = pack_bf16x2(h2, h3);
                    pl[mt][half * 2 + 0] = pack_bf16x2(p0 - h0, p1 - h1);
                    pl[mt][half * 2 + 1] = pack_bf16x2(p2 - h2, p3 - h3);
                }
                // reorder: a-frag wants {row g k, row g+8 k, row g k+8, row g+8 k+8}
                // built above as {g lo, g+8 lo | g hi, g+8 hi} -> already a0..a3 order
            }
            uint32_t vh[8][2], vl[8][2];
            #pragma unroll
            for (int np = 0; np < 4; np++) {
                const int r = np * 16 + brow_base;
                const uint32_t off = r * 128 + ((((kc << 1) | bkh) ^ (r & 7)) << 4);
                uint32_t q4[4];
                LDSM4(q4, sb + 16384 + off);
                vh[np * 2 + 0][0] = q4[0];  vh[np * 2 + 0][1] = q4[1];
                vh[np * 2 + 1][0] = q4[2];  vh[np * 2 + 1][1] = q4[3];
                LDSM4(q4, sb + 24576 + off);
                vl[np * 2 + 0][0] = q4[0];  vl[np * 2 + 0][1] = q4[1];
                vl[np * 2 + 1][0] = q4[2];  vl[np * 2 + 1][1] = q4[3];
            }
            #pragma unroll
            for (int mt = 0; mt < 2; mt++)
                #pragma unroll
                for (int nt = 0; nt < 8; nt++) {
                    mma16816(O[mt][nt], ph[mt], vh[nt]);
                    mma16816(O[mt][nt], ph[mt], vl[nt]);
                    mma16816(O[mt][nt], pl[mt], vh[nt]);
                }
        }

        // ---- pipeline advance ----
        __syncthreads();
        if (kt + 2 < nkt) load_kv(kt + 2, sb);
        cp_commit();
        cp_wait1();
        __syncthreads();
    }

    // ---- epilogue: y = O / l, written as bf16 hi/lo for the proj GEMM ----
    const int hcol = blockIdx.y * 64;
    #pragma unroll
    for (int mt = 0; mt < 2; mt++) {
        const float inv0 = 1.f / lrun[mt][0];
        const float inv1 = 1.f / lrun[mt][1];
        const int r0 = blockIdx.z * T_ + q0w + mt * 16 + g;
        #pragma unroll
        for (int nt = 0; nt < 8; nt++) {
            const size_t o0 = (size_t)r0 * C_ + hcol + nt * 8 + c2;
            const size_t o1 = o0 + (size_t)8 * C_;
            __nv_bfloat16 h0, h1, h2, h3, l0, l1, l2, l3;
            split2(O[mt][nt][0] * inv0, h0, l0);
            split2(O[mt][nt][1] * inv0, h1, l1);
            split2(O[mt][nt][2] * inv1, h2, l2);
            split2(O[mt][nt][3] * inv1, h3, l3);
            *(__nv_bfloat162*)(g_yhi + o0) = __halves2bfloat162(h0, h1);
            *(__nv_bfloat162*)(g_ylo + o0) = __halves2bfloat162(l0, l1);
            *(__nv_bfloat162*)(g_yhi + o1) = __halves2bfloat162(h2, h3);
            *(__nv_bfloat162*)(g_ylo + o1) = __halves2bfloat162(l2, l3);
        }
    }
}

// ---------------------------------------------------------------------------
extern "C" void kernel_launch(void* const* d_in, const int* in_sizes, int n_in,
                              void* d_out, int out_size)
{
    const float* x      = (const float*)d_in[0];
    const float* w_attn = (const float*)d_in[1];
    const float* w_proj = (const float*)d_in[2];
    float* out = (float*)d_out;

    static bool attr_done = false;
    if (!attr_done) {
        cudaFuncSetAttribute(qkv_gemm_tc,  cudaFuncAttributeMaxDynamicSharedMemorySize, GEMM_SMEM);
        cudaFuncSetAttribute(proj_gemm_tc, cudaFuncAttributeMaxDynamicSharedMemorySize, GEMM_SMEM);
        cudaFuncSetAttribute(attn_hmma_kernel, cudaFuncAttributeMaxDynamicSharedMemorySize, ATT_SMEM);
        attr_done = true;
    }

    __nv_bfloat16 *xhi, *xlo, *wahi, *walo, *wphi, *wplo;
    cudaGetSymbolAddress((void**)&xhi,  g_xhi);
    cudaGetSymbolAddress((void**)&xlo,  g_xlo);
    cudaGetSymbolAddress((void**)&wahi, g_wahi);
    cudaGetSymbolAddress((void**)&walo, g_walo);
    cudaGetSymbolAddress((void**)&wphi, g_wphi);
    cudaGetSymbolAddress((void**)&wplo, g_wplo);

    // 1) split x -> bf16 hi/lo
    split_kernel<<<(M_ * KD) / 1024, 256>>>(x, xhi, xlo, M_ * KD);
    // 2) transpose+split weights
    {
        dim3 grid(KD / 32, (3 * C_) / 32);
        splitT_kernel<<<grid, dim3(32, 8)>>>(w_attn, wahi, walo, KD, 3 * C_);
    }
    {
        dim3 grid(KD / 32, C_ / 32);
        splitT_kernel<<<grid, dim3(32, 8)>>>(w_proj, wphi, wplo, KD, C_);
    }
    // 3) QKV GEMM (HMMA bf16x3) -> g_qkv fp32
    {
        dim3 grid((3 * C_) / 128, M_ / 128);
        qkv_gemm_tc<<<grid, 256, GEMM_SMEM>>>();
    }
    // 4) repack to head-major bf16 hi/lo (Q scaled), V transposed
    repack_qk_kernel<<<(M_ * 2048) / 4 / 256, 256>>>();
    {
        dim3 grid(T_ / 32, DH / 32, B_ * H_);
        repack_vt_kernel<<<grid, dim3(32, 8)>>>();
    }
    // 5) HMMA flash attention -> g_yhi/g_ylo
    {
        dim3 grid(T_ / 128, H_, B_);
        attn_hmma_kernel<<<grid, 128, ATT_SMEM>>>();
    }
    // 6) proj GEMM (HMMA bf16x3) -> out
    {
        dim3 grid(C_ / 128, M_ / 128);
        proj_gemm_tc<<<grid, 256, GEMM_SMEM>>>(out);
    }
}

// round 6
// speedup vs baseline: 3.7363x; 1.0061x over previous
#include <cuda_runtime.h>
#include <cuda_bf16.h>
#include <cstdint>

#define B_  2
#define T_  2048
#define C_  1024
#define H_  16
#define DH  64
#define M_  (B_ * T_)
#define KD  1024

// ---------------- scratch (static device globals) ----------------
__device__ __nv_bfloat16 g_xhi[(size_t)M_ * KD];
__device__ __nv_bfloat16 g_xlo[(size_t)M_ * KD];
__device__ __nv_bfloat16 g_wahi[(size_t)3 * C_ * KD];   // W_attn^T [3072,1024]
__device__ __nv_bfloat16 g_walo[(size_t)3 * C_ * KD];
__device__ __nv_bfloat16 g_wphi[(size_t)C_ * KD];       // W_proj^T [1024,1024]
__device__ __nv_bfloat16 g_wplo[(size_t)C_ * KD];
__device__ __nv_bfloat16 g_yhi[(size_t)M_ * KD];        // attention out (hi)
__device__ __nv_bfloat16 g_ylo[(size_t)M_ * KD];        // attention out (lo)
// head-major attention operands (written by fused QKV epilogue)
__device__ __nv_bfloat16 g_qh[(size_t)B_ * H_ * T_ * DH];
__device__ __nv_bfloat16 g_ql[(size_t)B_ * H_ * T_ * DH];
__device__ __nv_bfloat16 g_kh[(size_t)B_ * H_ * T_ * DH];
__device__ __nv_bfloat16 g_kl[(size_t)B_ * H_ * T_ * DH];
__device__ __nv_bfloat16 g_vth[(size_t)B_ * H_ * DH * T_];   // transposed [bh][d][t]
__device__ __nv_bfloat16 g_vtl[(size_t)B_ * H_ * DH * T_];

// ---------------- base-ISA PTX helpers (sm_80+) ----------------
__device__ __forceinline__ uint32_t smem_u32(const void* p) {
    uint32_t a;
    asm("{ .reg .u64 t; cvta.to.shared.u64 t, %1; cvt.u32.u64 %0, t; }" : "=r"(a) : "l"(p));
    return a;
}
__device__ __forceinline__ void cp16(uint32_t s, const void* g) {
    asm volatile("cp.async.cg.shared.global [%0], [%1], 16;" :: "r"(s), "l"(g));
}
__device__ __forceinline__ void cp_commit() {
    asm volatile("cp.async.commit_group;" ::: "memory");
}
__device__ __forceinline__ void cp_wait1() {
    asm volatile("cp.async.wait_group 1;" ::: "memory");
}
__device__ __forceinline__ void cp_wait0() {
    asm volatile("cp.async.wait_group 0;" ::: "memory");
}
#define LDSM4(R, addr) \
    asm volatile("ldmatrix.sync.aligned.m8n8.x4.shared.b16 {%0,%1,%2,%3}, [%4];" \
                 : "=r"((R)[0]), "=r"((R)[1]), "=r"((R)[2]), "=r"((R)[3]) : "r"(addr))

__device__ __forceinline__ void mma16816(float* c, const uint32_t* a, const uint32_t* b) {
    asm volatile(
        "mma.sync.aligned.m16n8k16.row.col.f32.bf16.bf16.f32 "
        "{%0,%1,%2,%3}, {%4,%5,%6,%7}, {%8,%9}, {%0,%1,%2,%3};"
        : "+f"(c[0]), "+f"(c[1]), "+f"(c[2]), "+f"(c[3])
        : "r"(a[0]), "r"(a[1]), "r"(a[2]), "r"(a[3]), "r"(b[0]), "r"(b[1]));
}
__device__ __forceinline__ uint32_t pack_bf16x2(float lo, float hi) {
    uint32_t d;
    asm("cvt.rn.bf16x2.f32 %0, %1, %2;" : "=r"(d) : "f"(hi), "f"(lo));
    return d;
}

// ---------------- fp32 -> bf16 hi/lo split ----------------
__device__ __forceinline__ void split2(float v, __nv_bfloat16& h, __nv_bfloat16& l) {
    h = __float2bfloat16(v);
    l = __float2bfloat16(v - __bfloat162float(h));
}

__global__ __launch_bounds__(256)
void split_kernel(const float* __restrict__ in,
                  __nv_bfloat16* __restrict__ hi, __nv_bfloat16* __restrict__ lo, int n)
{
    int i = (blockIdx.x * 256 + threadIdx.x) * 4;
    if (i >= n) return;
    float4 v = *(const float4*)(in + i);
    __nv_bfloat16 h0, h1, h2, h3, l0, l1, l2, l3;
    split2(v.x, h0, l0); split2(v.y, h1, l1);
    split2(v.z, h2, l2); split2(v.w, h3, l3);
    *(__nv_bfloat162*)(hi + i)     = __halves2bfloat162(h0, h1);
    *(__nv_bfloat162*)(hi + i + 2) = __halves2bfloat162(h2, h3);
    *(__nv_bfloat162*)(lo + i)     = __halves2bfloat162(l0, l1);
    *(__nv_bfloat162*)(lo + i + 2) = __halves2bfloat162(l2, l3);
}

__global__ __launch_bounds__(256)
void splitT_kernel(const float* __restrict__ W,
                   __nv_bfloat16* __restrict__ hiT, __nv_bfloat16* __restrict__ loT,
                   int Kdim, int Ndim)
{
    __shared__ float tile[32][33];
    const int k0 = blockIdx.x * 32, n0 = blockIdx.y * 32;
    const int tx = threadIdx.x, ty = threadIdx.y;   // 32 x 8
    #pragma unroll
    for (int i = 0; i < 32; i += 8)
        tile[ty + i][tx] = W[(size_t)(k0 + ty + i) * Ndim + n0 + tx];
    __syncthreads();
    #pragma unroll
    for (int i = 0; i < 32; i += 8) {
        float v = tile[tx][ty + i];
        __nv_bfloat16 h, l;
        split2(v, h, l);
        size_t o = (size_t)(n0 + ty + i) * Kdim + k0 + tx;
        hiT[o] = h;
        loT[o] = l;
    }
}

// ---------------------------------------------------------------------------
// bf16x3 HMMA GEMM mainloop: 3-stage single-sync cp.async pipeline.
// CTA 128x128, 8 warps 2(M) x 4(N), BK=64 (128B SW128-swizzled rows).
// ---------------------------------------------------------------------------
#define MAT_BYTES   16384
#define STAGE_BYTES (4 * MAT_BYTES)
#define GEMM_SMEM   (3 * STAGE_BYTES)
#define NSTAGE      (KD / 64)

__device__ __forceinline__ void gemm_mainloop(
    const __nv_bfloat16* __restrict__ Ahi, const __nv_bfloat16* __restrict__ Alo,
    const __nv_bfloat16* __restrict__ Bhi, const __nv_bfloat16* __restrict__ Blo,
    int m0, int n0, uint32_t smem, float (&acc)[4][4][4])
{
    const int tid    = threadIdx.x;
    const int lane   = tid & 31;
    const int warp   = tid >> 5;
    const int warp_m = warp & 1;
    const int warp_n = warp >> 1;

    const __nv_bfloat16* mats[4] = { Ahi, Alo, Bhi, Blo };
    const int rowbase[2] = { m0, n0 };

    auto load_stage = [&](int kofs, uint32_t stage_u32) {
        #pragma unroll
        for (int t = 0; t < 16; t++) {
            const int mat = t >> 2;
            const int rem = ((t & 3) << 8) + tid;
            const int row = rem >> 3;
            const int ch  = tid & 7;
            const __nv_bfloat16* g = mats[mat]
                + (size_t)(rowbase[mat >> 1] + row) * KD + kofs + ch * 8;
            uint32_t s = stage_u32 + mat * MAT_BYTES + row * 128
                       + ((ch ^ (row & 7)) << 4);
            cp16(s, g);
        }
    };

    #pragma unroll
    for (int i = 0; i < 4; i++)
        #pragma unroll
        for (int j = 0; j < 4; j++)
            #pragma unroll
            for (int k = 0; k < 4; k++) acc[i][j][k] = 0.f;

    // prologue: stages 0,1 -> bufs 0,1
    load_stage(0, smem);
    cp_commit();
    load_stage(64, smem + STAGE_BYTES);
    cp_commit();

    const int arow = warp_m * 64 + (lane & 15);
    const int ah_  = lane >> 4;
    const int brow = warp_n * 32 + ((lane >> 4) << 3) + (lane & 7);
    const int bkh  = (lane >> 3) & 1;

    for (int ks = 0; ks < NSTAGE; ks++) {
        cp_wait1();            // stage ks resident (this thread's part)
        __syncthreads();       // everyone's part resident; buf ks-1 free

        // issue next load into the buffer freed by the barrier
        const uint32_t nb = smem + ((ks + 2) % 3) * STAGE_BYTES;
        if (ks + 2 < NSTAGE) load_stage((ks + 2) * 64, nb);
        else                 cp16(nb + tid * 16, Ahi + tid * 8);  // real dummy group
        cp_commit();

        const uint32_t sb = smem + (ks % 3) * STAGE_BYTES;
        #pragma unroll
        for (int kk = 0; kk < 4; kk++) {
            uint32_t ahf[4][4], alf[4][4], bhf[4][2], blf[4][2];
            #pragma unroll
            for (int mt = 0; mt < 4; mt++) {
                const int r = arow + mt * 16;
                const uint32_t off = r * 128 + ((((kk << 1) | ah_) ^ (r & 7)) << 4);
                LDSM4(ahf[mt], sb + off);
                LDSM4(alf[mt], sb + MAT_BYTES + off);
            }
            #pragma unroll
            for (int np = 0; np < 2; np++) {
                const int r = brow + np * 16;
                const uint32_t off = r * 128 + ((((kk << 1) | bkh) ^ (r & 7)) << 4);
                uint32_t q[4];
                LDSM4(q, sb + 2 * MAT_BYTES + off);
                bhf[np * 2 + 0][0] = q[0];  bhf[np * 2 + 0][1] = q[1];
                bhf[np * 2 + 1][0] = q[2];  bhf[np * 2 + 1][1] = q[3];
                LDSM4(q, sb + 3 * MAT_BYTES + off);
                blf[np * 2 + 0][0] = q[0];  blf[np * 2 + 0][1] = q[1];
                blf[np * 2 + 1][0] = q[2];  blf[np * 2 + 1][1] = q[3];
            }
            #pragma unroll
            for (int mt = 0; mt < 4; mt++)
                #pragma unroll
                for (int nt = 0; nt < 4; nt++) {
                    mma16816(acc[mt][nt], ahf[mt], bhf[nt]);
                    mma16816(acc[mt][nt], ahf[mt], blf[nt]);
                    mma16816(acc[mt][nt], alf[mt], bhf[nt]);
                }
        }
    }
}

// QKV GEMM with fused epilogue: writes head-major bf16 hi/lo (Q scaled 0.125),
// V transposed through smem. No fp32 intermediate.
__global__ __launch_bounds__(256, 1)
void qkv_gemm_tc()
{
    extern __shared__ __align__(128) char smem_raw[];
    const uint32_t smem = smem_u32(smem_raw);
    const int m0 = blockIdx.y * 128;
    const int n0 = blockIdx.x * 128;

    float acc[4][4][4];
    gemm_mainloop(g_xhi, g_xlo, g_wahi, g_walo, m0, n0, smem, acc);

    const int tid  = threadIdx.x;
    const int lane = tid & 31;
    const int warp = tid >> 5;
    const int warp_m = warp & 1;
    const int warp_n = warp >> 1;
    const int g  = lane >> 2;
    const int tg = lane & 3;
    const int bb = m0 >> 11;         // batch
    const int t0 = m0 & 2047;        // base time index

    const int sect = n0 >> 10;       // 0=Q, 1=K, 2=V
    if (sect < 2) {
        const float sc = (sect == 0) ? 0.125f : 1.f;
        __nv_bfloat16* hi = (sect == 0) ? g_qh : g_kh;
        __nv_bfloat16* lo = (sect == 0) ? g_ql : g_kl;
        const int nc = n0 & 1023;
        #pragma unroll
        for (int mt = 0; mt < 4; mt++) {
            #pragma unroll
            for (int nt = 0; nt < 4; nt++) {
                const int c  = nc + warp_n * 32 + nt * 8 + tg * 2;
                const int hh = c >> 6, d = c & 63;
                const int r  = warp_m * 64 + mt * 16 + g;
                const size_t base = ((size_t)(bb * H_ + hh) * T_ + t0 + r) * DH + d;
                __nv_bfloat16 h0, h1, h2, h3, l0, l1, l2, l3;
                split2(acc[mt][nt][0] * sc, h0, l0);
                split2(acc[mt][nt][1] * sc, h1, l1);
                split2(acc[mt][nt][2] * sc, h2, l2);
                split2(acc[mt][nt][3] * sc, h3, l3);
                *(__nv_bfloat162*)(hi + base) = __halves2bfloat162(h0, h1);
                *(__nv_bfloat162*)(lo + base) = __halves2bfloat162(l0, l1);
                *(__nv_bfloat162*)(hi + base + 8 * DH) = __halves2bfloat162(h2, h3);
                *(__nv_bfloat162*)(lo + base + 8 * DH) = __halves2bfloat162(l2, l3);
            }
        }
    } else {
        // V: transpose through smem (stride 130 floats: conflict-free both ways)
        cp_wait0();
        __syncthreads();           // all cp.async drained; smem reusable
        float* sf = (float*)smem_raw;
        #pragma unroll
        for (int mt = 0; mt < 4; mt++) {
            #pragma unroll
            for (int nt = 0; nt < 4; nt++) {
                const int r = warp_m * 64 + mt * 16 + g;
                const int c = warp_n * 32 + nt * 8 + tg * 2;
                sf[r * 130 + c]           = acc[mt][nt][0];
                sf[r * 130 + c + 1]       = acc[mt][nt][1];
                sf[(r + 8) * 130 + c]     = acc[mt][nt][2];
                sf[(r + 8) * 130 + c + 1] = acc[mt][nt][3];
            }
        }
        __syncthreads();
        const int dl = tid & 127;     // local col (d within 128-wide tile)
        const int th = tid >> 7;      // t-half (0/1)
        const int nv = (n0 - 2048) + dl;
        const int hh = nv >> 6, d = nv & 63;
        const size_t ob = ((size_t)(bb * H_ + hh) * DH + d) * T_ + t0 + th * 64;
        #pragma unroll
        for (int i = 0; i < 64; i += 2) {
            const float v0 = sf[(th * 64 + i) * 130 + dl];
            const float v1 = sf[(th * 64 + i + 1) * 130 + dl];
            __nv_bfloat16 h0, h1, l0, l1;
            split2(v0, h0, l0);
            split2(v1, h1, l1);
            *(__nv_bfloat162*)(g_vth + ob + i) = __halves2bfloat162(h0, h1);
            *(__nv_bfloat162*)(g_vtl + ob + i) = __halves2bfloat162(l0, l1);
        }
    }
}

// proj GEMM: plain fp32 epilogue to d_out
__global__ __launch_bounds__(256, 1)
void proj_gemm_tc(float* __restrict__ out)
{
    extern __shared__ __align__(128) char smem_raw[];
    const uint32_t smem = smem_u32(smem_raw);
    const int m0 = blockIdx.y * 128;
    const int n0 = blockIdx.x * 128;

    float acc[4][4][4];
    gemm_mainloop(g_yhi, g_ylo, g_wphi, g_wplo, m0, n0, smem, acc);

    const int lane = threadIdx.x & 31;
    const int warp = threadIdx.x >> 5;
    const int warp_m = warp & 1;
    const int warp_n = warp >> 1;
    const int g  = lane >> 2;
    const int tg = lane & 3;
    #pragma unroll
    for (int mt = 0; mt < 4; mt++) {
        #pragma unroll
        for (int nt = 0; nt < 4; nt++) {
            const int row = m0 + warp_m * 64 + mt * 16 + g;
            const int col = n0 + warp_n * 32 + nt * 8 + tg * 2;
            *(float2*)(out + (size_t)row * C_ + col) =
                make_float2(acc[mt][nt][0], acc[mt][nt][1]);
            *(float2*)(out + (size_t)(row + 8) * C_ + col) =
                make_float2(acc[mt][nt][2], acc[mt][nt][3]);
        }
    }
}

// ---------------------------------------------------------------------------
// HMMA flash attention: CTA = 128 queries x one (b,h). 4 warps.
// 3-stage single-sync cp.async pipeline over K/V tiles of 64 keys.
// smem: Q hi/lo 32KB + 3 stages x 32KB = 128KB.
// ---------------------------------------------------------------------------
#define ATT_STAGE 32768
#define ATT_SMEM  (32768 + 3 * ATT_STAGE)

__global__ __launch_bounds__(128, 1)
void attn_hmma_kernel()
{
    extern __shared__ __align__(128) char smem_raw[];
    const uint32_t smem = smem_u32(smem_raw);
    const uint32_t qsm  = smem;
    const uint32_t st0  = smem + 32768;

    const int tid  = threadIdx.x;
    const int lane = tid & 31;
    const int warp = tid >> 5;
    const int qt   = (gridDim.x - 1) - blockIdx.x;   // heavy first
    const int bh   = blockIdx.z * H_ + blockIdx.y;
    const size_t qkb = (size_t)bh * T_ * DH;
    const size_t vb  = (size_t)bh * DH * T_;
    const int nkt = 2 * (qt + 1);

    // Q tile load (once; part of group 0)
    {
        const __nv_bfloat16* s0 = g_qh + qkb + (size_t)qt * 128 * DH;
        const __nv_bfloat16* s1 = g_ql + qkb + (size_t)qt * 128 * DH;
        #pragma unroll
        for (int t = 0; t < 16; t++) {
            const int rem = ((t & 7) << 7) + tid;
            const int row = rem >> 3, ch = rem & 7;
            const __nv_bfloat16* g = ((t >> 3) ? s1 : s0) + (size_t)row * DH + ch * 8;
            cp16(qsm + (t >> 3) * 16384 + row * 128 + ((ch ^ (row & 7)) << 4), g);
        }
    }
    auto load_kv = [&](int kt, uint32_t stage) {
        #pragma unroll
        for (int t = 0; t < 16; t++) {
            const int mat = t >> 2;
            const int rem = ((t & 3) << 7) + tid;
            const int row = rem >> 3, ch = rem & 7;
            const __nv_bfloat16* g;
            if (mat == 0)      g = g_kh  + qkb + (size_t)(kt * 64 + row) * DH + ch * 8;
            else if (mat == 1) g = g_kl  + qkb + (size_t)(kt * 64 + row) * DH + ch * 8;
            else if (mat == 2) g = g_vth + vb  + (size_t)row * T_ + kt * 64 + ch * 8;
            else               g = g_vtl + vb  + (size_t)row * T_ + kt * 64 + ch * 8;
            cp16(stage + mat * 8192 + row * 128 + ((ch ^ (row & 7)) << 4), g);
        }
    };

    load_kv(0, st0);
    cp_commit();                 // group: Q + kv0
    load_kv(1, st0 + ATT_STAGE);
    cp_commit();                 // group: kv1

    const int g   = lane >> 2;
    const int c2  = (lane & 3) * 2;
    const int q0w = qt * 128 + warp * 32;
    const int bkh = (lane >> 3) & 1;
    const int ah_ = lane >> 4;
    const int brow_base = ((lane >> 4) << 3) + (lane & 7);

    float O[2][8][4];
    #pragma unroll
    for (int mt = 0; mt < 2; mt++)
        #pragma unroll
        for (int nt = 0; nt < 8; nt++)
            #pragma unroll
            for (int i = 0; i < 4; i++) O[mt][nt][i] = 0.f;
    float mrun[2][2] = {{-1e30f, -1e30f}, {-1e30f, -1e30f}};
    float lrun[2][2] = {{0.f, 0.f}, {0.f, 0.f}};

    for (int kt = 0; kt < nkt; kt++) {
        cp_wait1();
        __syncthreads();

        // prefetch kt+2 into the buffer freed by the barrier
        const uint32_t nb = st0 + ((kt + 2) % 3) * ATT_STAGE;
        if (kt + 2 < nkt) load_kv(kt + 2, nb);
        else              cp16(nb + tid * 16, g_kh + tid * 8);   // real dummy
        cp_commit();

        const uint32_t sb = st0 + (kt % 3) * ATT_STAGE;

        float sacc[2][8][4];
        #pragma unroll
        for (int mt = 0; mt < 2; mt++)
            #pragma unroll
            for (int nt = 0; nt < 8; nt++)
                #pragma unroll
                for (int i = 0; i < 4; i++) sacc[mt][nt][i] = 0.f;

        // ---- S = Q K^T (bf16x3) ----
        #pragma unroll
        for (int kk = 0; kk < 4; kk++) {
            uint32_t qhf[2][4], qlf[2][4];
            #pragma unroll
            for (int mt = 0; mt < 2; mt++) {
                const int r = warp * 32 + mt * 16 + (lane & 15);
                const uint32_t off = r * 128 + ((((kk << 1) | ah_) ^ (r & 7)) << 4);
                LDSM4(qhf[mt], qsm + off);
                LDSM4(qlf[mt], qsm + 16384 + off);
            }
            uint32_t khf[8][2], klf[8][2];
            #pragma unroll
            for (int np = 0; np < 4; np++) {
                const int r = np * 16 + brow_base;
                const uint32_t off = r * 128 + ((((kk << 1) | bkh) ^ (r & 7)) << 4);
                uint32_t q4[4];
                LDSM4(q4, sb + off);
                khf[np * 2 + 0][0] = q4[0];  khf[np * 2 + 0][1] = q4[1];
                khf[np * 2 + 1][0] = q4[2];  khf[np * 2 + 1][1] = q4[3];
                LDSM4(q4, sb + 8192 + off);
                klf[np * 2 + 0][0] = q4[0];  klf[np * 2 + 0][1] = q4[1];
                klf[np * 2 + 1][0] = q4[2];  klf[np * 2 + 1][1] = q4[3];
            }
            #pragma unroll
            for (int mt = 0; mt < 2; mt++)
                #pragma unroll
                for (int nt = 0; nt < 8; nt++) {
                    mma16816(sacc[mt][nt], qhf[mt], khf[nt]);
                    mma16816(sacc[mt][nt], qhf[mt], klf[nt]);
                    mma16816(sacc[mt][nt], qlf[mt], khf[nt]);
                }
        }

        // ---- causal mask (diagonal tiles only) ----
        if (kt >= 2 * qt) {
            const int kt64 = kt * 64;
            #pragma unroll
            for (int mt = 0; mt < 2; mt++) {
                const int qr0 = q0w + mt * 16 + g;
                #pragma unroll
                for (int nt = 0; nt < 8; nt++) {
                    const int kc = kt64 + nt * 8 + c2;
                    if (kc > qr0)         sacc[mt][nt][0] = -1e30f;
                    if (kc + 1 > qr0)     sacc[mt][nt][1] = -1e30f;
                    if (kc > qr0 + 8)     sacc[mt][nt][2] = -1e30f;
                    if (kc + 1 > qr0 + 8) sacc[mt][nt][3] = -1e30f;
                }
            }
        }

        // ---- online softmax ----
        #pragma unroll
        for (int mt = 0; mt < 2; mt++) {
            float h0 = -1e30f, h1 = -1e30f;
            #pragma unroll
            for (int nt = 0; nt < 8; nt++) {
                h0 = fmaxf(h0, fmaxf(sacc[mt][nt][0], sacc[mt][nt][1]));
                h1 = fmaxf(h1, fmaxf(sacc[mt][nt][2], sacc[mt][nt][3]));
            }
            h0 = fmaxf(h0, __shfl_xor_sync(0xffffffffu, h0, 1));
            h0 = fmaxf(h0, __shfl_xor_sync(0xffffffffu, h0, 2));
            h1 = fmaxf(h1, __shfl_xor_sync(0xffffffffu, h1, 1));
            h1 = fmaxf(h1, __shfl_xor_sync(0xffffffffu, h1, 2));
            const float m0 = fmaxf(mrun[mt][0], h0);
            const float m1 = fmaxf(mrun[mt][1], h1);
            const float a0 = __expf(mrun[mt][0] - m0);
            const float a1 = __expf(mrun[mt][1] - m1);
            mrun[mt][0] = m0;  mrun[mt][1] = m1;

            float s0 = 0.f, s1 = 0.f;
            #pragma unroll
            for (int nt = 0; nt < 8; nt++) {
                float p0 = __expf(sacc[mt][nt][0] - m0);
                float p1 = __expf(sacc[mt][nt][1] - m0);
                float p2 = __expf(sacc[mt][nt][2] - m1);
                float p3 = __expf(sacc[mt][nt][3] - m1);
                sacc[mt][nt][0] = p0;  sacc[mt][nt][1] = p1;
                sacc[mt][nt][2] = p2;  sacc[mt][nt][3] = p3;
                s0 += p0 + p1;
                s1 += p2 + p3;
            }
            s0 += __shfl_xor_sync(0xffffffffu, s0, 1);
            s0 += __shfl_xor_sync(0xffffffffu, s0, 2);
            s1 += __shfl_xor_sync(0xffffffffu, s1, 1);
            s1 += __shfl_xor_sync(0xffffffffu, s1, 2);
            lrun[mt][0] = lrun[mt][0] * a0 + s0;
            lrun[mt][1] = lrun[mt][1] * a1 + s1;

            #pragma unroll
            for (int nt = 0; nt < 8; nt++) {
                O[mt][nt][0] *= a0;
                O[mt][nt][1] *= a0;
                O[mt][nt][2] *= a1;
                O[mt][nt][3] *= a1;
            }
        }

        // ---- O += P V (bf16x3, P hi/lo in registers) ----
        #pragma unroll
        for (int kc = 0; kc < 4; kc++) {
            uint32_t ph[2][4], pl[2][4];
            #pragma unroll
            for (int mt = 0; mt < 2; mt++) {
                #pragma unroll
                for (int half = 0; half < 2; half++) {
                    const int nt = 2 * kc + half;
                    float p0 = sacc[mt][nt][0], p1 = sacc[mt][nt][1];
                    float p2 = sacc[mt][nt][2], p3 = sacc[mt][nt][3];
                    float h0 = __bfloat162float(__float2bfloat16(p0));
                    float h1 = __bfloat162float(__float2bfloat16(p1));
                    float h2 = __bfloat162float(__float2bfloat16(p2));
                    float h3 = __bfloat162float(__float2bfloat16(p3));
                    ph[mt][half * 2 + 0] = pack_bf16x2(h0, h1);
                    ph[mt][half * 2 + 1] = pack_bf16x2(h2, h3);
                    pl[mt][half * 2 + 0] = pack_bf16x2(p0 - h0, p1 - h1);
                    pl[mt][half * 2 + 1] = pack_bf16x2(p2 - h2, p3 - h3);
                }
            }
            uint32_t vh[8][2], vl[8][2];
            #pragma unroll
            for (int np = 0; np < 4; np++) {
                const int r = np * 16 + brow_base;
                const uint32_t off = r * 128 + ((((kc << 1) | bkh) ^ (r & 7)) << 4);
                uint32_t q4[4];
                LDSM4(q4, sb + 16384 + off);
                vh[np * 2 + 0][0] = q4[0];  vh[np * 2 + 0][1] = q4[1];
                vh[np * 2 + 1][0] = q4[2];  vh[np * 2 + 1][1] = q4[3];
                LDSM4(q4, sb + 24576 + off);
                vl[np * 2 + 0][0] = q4[0];  vl[np * 2 + 0][1] = q4[1];
                vl[np * 2 + 1][0] = q4[2];  vl[np * 2 + 1][1] = q4[3];
            }
            #pragma unroll
            for (int mt = 0; mt < 2; mt++)
                #pragma unroll
                for (int nt = 0; nt < 8; nt++) {
                    mma16816(O[mt][nt], ph[mt], vh[nt]);
                    mma16816(O[mt][nt], ph[mt], vl[nt]);
                    mma16816(O[mt][nt], pl[mt], vh[nt]);
                }
        }
    }

    // ---- epilogue: y = O / l, written as bf16 hi/lo for the proj GEMM ----
    const int hcol = blockIdx.y * 64;
    #pragma unroll
    for (int mt = 0; mt < 2; mt++) {
        const float inv0 = 1.f / lrun[mt][0];
        const float inv1 = 1.f / lrun[mt][1];
        const int r0 = blockIdx.z * T_ + q0w + mt * 16 + g;
        #pragma unroll
        for (int nt = 0; nt < 8; nt++) {
            const size_t o0 = (size_t)r0 * C_ + hcol + nt * 8 + c2;
            const size_t o1 = o0 + (size_t)8 * C_;
            __nv_bfloat16 h0, h1, h2, h3, l0, l1, l2, l3;
            split2(O[mt][nt][0] * inv0, h0, l0);
            split2(O[mt][nt][1] * inv0, h1, l1);
            split2(O[mt][nt][2] * inv1, h2, l2);
            split2(O[mt][nt][3] * inv1, h3, l3);
            *(__nv_bfloat162*)(g_yhi + o0) = __halves2bfloat162(h0, h1);
            *(__nv_bfloat162*)(g_ylo + o0) = __halves2bfloat162(l0, l1);
            *(__nv_bfloat162*)(g_yhi + o1) = __halves2bfloat162(h2, h3);
            *(__nv_bfloat162*)(g_ylo + o1) = __halves2bfloat162(l2, l3);
        }
    }
}

// ---------------------------------------------------------------------------
extern "C" void kernel_launch(void* const* d_in, const int* in_sizes, int n_in,
                              void* d_out, int out_size)
{
    const float* x      = (const float*)d_in[0];
    const float* w_attn = (const float*)d_in[1];
    const float* w_proj = (const float*)d_in[2];
    float* out = (float*)d_out;

    static bool attr_done = false;
    if (!attr_done) {
        cudaFuncSetAttribute(qkv_gemm_tc,  cudaFuncAttributeMaxDynamicSharedMemorySize, GEMM_SMEM);
        cudaFuncSetAttribute(proj_gemm_tc, cudaFuncAttributeMaxDynamicSharedMemorySize, GEMM_SMEM);
        cudaFuncSetAttribute(attn_hmma_kernel, cudaFuncAttributeMaxDynamicSharedMemorySize, ATT_SMEM);
        attr_done = true;
    }

    __nv_bfloat16 *xhi, *xlo, *wahi, *walo, *wphi, *wplo;
    cudaGetSymbolAddress((void**)&xhi,  g_xhi);
    cudaGetSymbolAddress((void**)&xlo,  g_xlo);
    cudaGetSymbolAddress((void**)&wahi, g_wahi);
    cudaGetSymbolAddress((void**)&walo, g_walo);
    cudaGetSymbolAddress((void**)&wphi, g_wphi);
    cudaGetSymbolAddress((void**)&wplo, g_wplo);

    // 1) split x -> bf16 hi/lo
    split_kernel<<<(M_ * KD) / 1024, 256>>>(x, xhi, xlo, M_ * KD);
    // 2) transpose+split weights
    {
        dim3 grid(KD / 32, (3 * C_) / 32);
        splitT_kernel<<<grid, dim3(32, 8)>>>(w_attn, wahi, walo, KD, 3 * C_);
    }
    {
        dim3 grid(KD / 32, C_ / 32);
        splitT_kernel<<<grid, dim3(32, 8)>>>(w_proj, wphi, wplo, KD, C_);
    }
    // 3) QKV GEMM (HMMA bf16x3) with fused head-major split epilogue
    {
        dim3 grid((3 * C_) / 128, M_ / 128);
        qkv_gemm_tc<<<grid, 256, GEMM_SMEM>>>();
    }
    // 4) HMMA flash attention -> g_yhi/g_ylo
    {
        dim3 grid(T_ / 128, H_, B_);
        attn_hmma_kernel<<<grid, 128, ATT_SMEM>>>();
    }
    // 5) proj GEMM (HMMA bf16x3) -> out
    {
        dim3 grid(C_ / 128, M_ / 128);
        proj_gemm_tc<<<grid, 256, GEMM_SMEM>>>(out);
    }
}

// round 7
// speedup vs baseline: 3.8505x; 1.0306x over previous
#include <cuda_runtime.h>
#include <cuda_bf16.h>
#include <cstdint>

#define B_  2
#define T_  2048
#define C_  1024
#define H_  16
#define DH  64
#define M_  (B_ * T_)
#define KD  1024

// ---------------- scratch (static device globals) ----------------
__device__ __nv_bfloat16 g_xhi[(size_t)M_ * KD];
__device__ __nv_bfloat16 g_xlo[(size_t)M_ * KD];
__device__ __nv_bfloat16 g_wahi[(size_t)3 * C_ * KD];   // W_attn^T [3072,1024]
__device__ __nv_bfloat16 g_walo[(size_t)3 * C_ * KD];
__device__ __nv_bfloat16 g_wphi[(size_t)C_ * KD];       // W_proj^T [1024,1024]
__device__ __nv_bfloat16 g_wplo[(size_t)C_ * KD];
__device__ __nv_bfloat16 g_yhi[(size_t)M_ * KD];        // attention out (hi)
__device__ __nv_bfloat16 g_ylo[(size_t)M_ * KD];        // attention out (lo)
// head-major attention operands (written by fused QKV epilogue)
__device__ __nv_bfloat16 g_qh[(size_t)B_ * H_ * T_ * DH];
__device__ __nv_bfloat16 g_ql[(size_t)B_ * H_ * T_ * DH];
__device__ __nv_bfloat16 g_kh[(size_t)B_ * H_ * T_ * DH];
__device__ __nv_bfloat16 g_kl[(size_t)B_ * H_ * T_ * DH];
__device__ __nv_bfloat16 g_vth[(size_t)B_ * H_ * DH * T_];   // transposed [bh][d][t]
__device__ __nv_bfloat16 g_vtl[(size_t)B_ * H_ * DH * T_];

// ---------------- base-ISA PTX helpers (sm_80+) ----------------
__device__ __forceinline__ uint32_t smem_u32(const void* p) {
    uint32_t a;
    asm("{ .reg .u64 t; cvta.to.shared.u64 t, %1; cvt.u32.u64 %0, t; }" : "=r"(a) : "l"(p));
    return a;
}
__device__ __forceinline__ void cp16(uint32_t s, const void* g) {
    asm volatile("cp.async.cg.shared.global [%0], [%1], 16;" :: "r"(s), "l"(g));
}
__device__ __forceinline__ void cp_commit() {
    asm volatile("cp.async.commit_group;" ::: "memory");
}
__device__ __forceinline__ void cp_wait1() {
    asm volatile("cp.async.wait_group 1;" ::: "memory");
}
__device__ __forceinline__ void cp_wait0() {
    asm volatile("cp.async.wait_group 0;" ::: "memory");
}
#define LDSM4(R, addr) \
    asm volatile("ldmatrix.sync.aligned.m8n8.x4.shared.b16 {%0,%1,%2,%3}, [%4];" \
                 : "=r"((R)[0]), "=r"((R)[1]), "=r"((R)[2]), "=r"((R)[3]) : "r"(addr))

__device__ __forceinline__ void mma16816(float* c, const uint32_t* a, const uint32_t* b) {
    asm volatile(
        "mma.sync.aligned.m16n8k16.row.col.f32.bf16.bf16.f32 "
        "{%0,%1,%2,%3}, {%4,%5,%6,%7}, {%8,%9}, {%0,%1,%2,%3};"
        : "+f"(c[0]), "+f"(c[1]), "+f"(c[2]), "+f"(c[3])
        : "r"(a[0]), "r"(a[1]), "r"(a[2]), "r"(a[3]), "r"(b[0]), "r"(b[1]));
}
__device__ __forceinline__ uint32_t pack_bf16x2(float lo, float hi) {
    uint32_t d;
    asm("cvt.rn.bf16x2.f32 %0, %1, %2;" : "=r"(d) : "f"(hi), "f"(lo));
    return d;
}

// ---------------- fp32 -> bf16 hi/lo split ----------------
__device__ __forceinline__ void split2(float v, __nv_bfloat16& h, __nv_bfloat16& l) {
    h = __float2bfloat16(v);
    l = __float2bfloat16(v - __bfloat162float(h));
}

__global__ __launch_bounds__(256)
void split_kernel(const float* __restrict__ in,
                  __nv_bfloat16* __restrict__ hi, __nv_bfloat16* __restrict__ lo, int n)
{
    int i = (blockIdx.x * 256 + threadIdx.x) * 4;
    if (i >= n) return;
    float4 v = *(const float4*)(in + i);
    __nv_bfloat16 h0, h1, h2, h3, l0, l1, l2, l3;
    split2(v.x, h0, l0); split2(v.y, h1, l1);
    split2(v.z, h2, l2); split2(v.w, h3, l3);
    *(__nv_bfloat162*)(hi + i)     = __halves2bfloat162(h0, h1);
    *(__nv_bfloat162*)(hi + i + 2) = __halves2bfloat162(h2, h3);
    *(__nv_bfloat162*)(lo + i)     = __halves2bfloat162(l0, l1);
    *(__nv_bfloat162*)(lo + i + 2) = __halves2bfloat162(l2, l3);
}

__global__ __launch_bounds__(256)
void splitT_kernel(const float* __restrict__ W,
                   __nv_bfloat16* __restrict__ hiT, __nv_bfloat16* __restrict__ loT,
                   int Kdim, int Ndim)
{
    __shared__ float tile[32][33];
    const int k0 = blockIdx.x * 32, n0 = blockIdx.y * 32;
    const int tx = threadIdx.x, ty = threadIdx.y;   // 32 x 8
    #pragma unroll
    for (int i = 0; i < 32; i += 8)
        tile[ty + i][tx] = W[(size_t)(k0 + ty + i) * Ndim + n0 + tx];
    __syncthreads();
    #pragma unroll
    for (int i = 0; i < 32; i += 8) {
        float v = tile[tx][ty + i];
        __nv_bfloat16 h, l;
        split2(v, h, l);
        size_t o = (size_t)(n0 + ty + i) * Kdim + k0 + tx;
        hiT[o] = h;
        loT[o] = l;
    }
}

// ---------------------------------------------------------------------------
// bf16x3 HMMA GEMM mainloop: CTA 128(M) x 256(N), 8 warps 2(M) x 4(N),
// warp tile 64x64, BK=64. 2-stage cp.async pipeline (round-5 ordering).
// Per-stage smem: Ahi 16K | Alo 16K | Bhi 32K | Blo 32K = 96KB.
// ---------------------------------------------------------------------------
#define A_BYTES     16384
#define B_BYTES     32768
#define STAGE_BYTES 98304
#define GEMM_SMEM   (2 * STAGE_BYTES)
#define NSTAGE      (KD / 64)

__device__ __forceinline__ void gemm_mainloop(
    const __nv_bfloat16* __restrict__ Ahi, const __nv_bfloat16* __restrict__ Alo,
    const __nv_bfloat16* __restrict__ Bhi, const __nv_bfloat16* __restrict__ Blo,
    int m0, int n0, uint32_t smem, float (&acc)[4][8][4])
{
    const int tid    = threadIdx.x;
    const int lane   = tid & 31;
    const int warp   = tid >> 5;
    const int warp_m = warp & 1;
    const int warp_n = warp >> 1;

    auto load_stage = [&](int kofs, uint32_t st) {
        // A hi/lo: 128 rows each
        #pragma unroll
        for (int t = 0; t < 8; t++) {
            const int mat = t >> 2;
            const int rem = ((t & 3) << 8) + tid;     // 0..1023
            const int row = rem >> 3;
            const int ch  = tid & 7;
            const __nv_bfloat16* g = (mat ? Alo : Ahi)
                + (size_t)(m0 + row) * KD + kofs + ch * 8;
            cp16(st + mat * A_BYTES + row * 128 + ((ch ^ (row & 7)) << 4), g);
        }
        // B hi/lo: 256 rows each
        #pragma unroll
        for (int t = 0; t < 16; t++) {
            const int mat = t >> 3;
            const int rem = ((t & 7) << 8) + tid;     // 0..2047
            const int row = rem >> 3;
            const int ch  = tid & 7;
            const __nv_bfloat16* g = (mat ? Blo : Bhi)
                + (size_t)(n0 + row) * KD + kofs + ch * 8;
            cp16(st + 2 * A_BYTES + mat * B_BYTES + row * 128 + ((ch ^ (row & 7)) << 4), g);
        }
    };

    #pragma unroll
    for (int i = 0; i < 4; i++)
        #pragma unroll
        for (int j = 0; j < 8; j++)
            #pragma unroll
            for (int k = 0; k < 4; k++) acc[i][j][k] = 0.f;

    load_stage(0, smem);
    cp_commit();
    load_stage(64, smem + STAGE_BYTES);
    cp_commit();
    cp_wait1();
    __syncthreads();

    const int arow = warp_m * 64 + (lane & 15);
    const int ah_  = lane >> 4;
    const int brow = warp_n * 64 + ((lane >> 4) << 3) + (lane & 7);
    const int bkh  = (lane >> 3) & 1;

    for (int ks = 0; ks < NSTAGE; ks++) {
        const uint32_t sb = smem + (ks & 1) * STAGE_BYTES;

        #pragma unroll
        for (int kk = 0; kk < 4; kk++) {
            uint32_t ahf[4][4], alf[4][4], bhf[8][2], blf[8][2];
            #pragma unroll
            for (int mt = 0; mt < 4; mt++) {
                const int r = arow + mt * 16;
                const uint32_t off = r * 128 + ((((kk << 1) | ah_) ^ (r & 7)) << 4);
                LDSM4(ahf[mt], sb + off);
                LDSM4(alf[mt], sb + A_BYTES + off);
            }
            #pragma unroll
            for (int np = 0; np < 4; np++) {
                const int r = brow + np * 16;
                const uint32_t off = r * 128 + ((((kk << 1) | bkh) ^ (r & 7)) << 4);
                uint32_t q[4];
                LDSM4(q, sb + 2 * A_BYTES + off);
                bhf[np * 2 + 0][0] = q[0];  bhf[np * 2 + 0][1] = q[1];
                bhf[np * 2 + 1][0] = q[2];  bhf[np * 2 + 1][1] = q[3];
                LDSM4(q, sb + 2 * A_BYTES + B_BYTES + off);
                blf[np * 2 + 0][0] = q[0];  blf[np * 2 + 0][1] = q[1];
                blf[np * 2 + 1][0] = q[2];  blf[np * 2 + 1][1] = q[3];
            }
            #pragma unroll
            for (int mt = 0; mt < 4; mt++)
                #pragma unroll
                for (int nt = 0; nt < 8; nt++) {
                    mma16816(acc[mt][nt], ahf[mt], bhf[nt]);
                    mma16816(acc[mt][nt], ahf[mt], blf[nt]);
                    mma16816(acc[mt][nt], alf[mt], bhf[nt]);
                }
        }

        __syncthreads();
        if (ks + 2 < NSTAGE) load_stage((ks + 2) * 64, sb);
        cp_commit();
        cp_wait1();
        __syncthreads();
    }
}

// QKV GEMM with fused epilogue: writes head-major bf16 hi/lo (Q scaled 0.125),
// V transposed through smem.
__global__ __launch_bounds__(256, 1)
void qkv_gemm_tc()
{
    extern __shared__ __align__(128) char smem_raw[];
    const uint32_t smem = smem_u32(smem_raw);
    const int m0 = blockIdx.y * 128;
    const int n0 = blockIdx.x * 256;

    float acc[4][8][4];
    gemm_mainloop(g_xhi, g_xlo, g_wahi, g_walo, m0, n0, smem, acc);

    const int tid  = threadIdx.x;
    const int lane = tid & 31;
    const int warp = tid >> 5;
    const int warp_m = warp & 1;
    const int warp_n = warp >> 1;
    const int g  = lane >> 2;
    const int tg = lane & 3;
    const int bb = m0 >> 11;
    const int t0 = m0 & 2047;

    const int sect = n0 >> 10;       // 0,1,2 (256 divides 1024: no straddle)
    if (sect < 2) {
        const float sc = (sect == 0) ? 0.125f : 1.f;
        __nv_bfloat16* hi = (sect == 0) ? g_qh : g_kh;
        __nv_bfloat16* lo = (sect == 0) ? g_ql : g_kl;
        const int nc = n0 & 1023;
        #pragma unroll
        for (int mt = 0; mt < 4; mt++) {
            #pragma unroll
            for (int nt = 0; nt < 8; nt++) {
                const int c  = nc + warp_n * 64 + nt * 8 + tg * 2;
                const int hh = c >> 6, d = c & 63;
                const int r  = warp_m * 64 + mt * 16 + g;
                const size_t base = ((size_t)(bb * H_ + hh) * T_ + t0 + r) * DH + d;
                __nv_bfloat16 h0, h1, h2, h3, l0, l1, l2, l3;
                split2(acc[mt][nt][0] * sc, h0, l0);
                split2(acc[mt][nt][1] * sc, h1, l1);
                split2(acc[mt][nt][2] * sc, h2, l2);
                split2(acc[mt][nt][3] * sc, h3, l3);
                *(__nv_bfloat162*)(hi + base) = __halves2bfloat162(h0, h1);
                *(__nv_bfloat162*)(lo + base) = __halves2bfloat162(l0, l1);
                *(__nv_bfloat162*)(hi + base + 8 * DH) = __halves2bfloat162(h2, h3);
                *(__nv_bfloat162*)(lo + base + 8 * DH) = __halves2bfloat162(l2, l3);
            }
        }
    } else {
        // V: transpose 128x256 tile through smem (stride 257: conflict-free reads)
        cp_wait0();
        __syncthreads();
        float* sf = (float*)smem_raw;
        #pragma unroll
        for (int mt = 0; mt < 4; mt++) {
            #pragma unroll
            for (int nt = 0; nt < 8; nt++) {
                const int r = warp_m * 64 + mt * 16 + g;
                const int c = warp_n * 64 + nt * 8 + tg * 2;
                sf[r * 257 + c]           = acc[mt][nt][0];
                sf[r * 257 + c + 1]       = acc[mt][nt][1];
                sf[(r + 8) * 257 + c]     = acc[mt][nt][2];
                sf[(r + 8) * 257 + c + 1] = acc[mt][nt][3];
            }
        }
        __syncthreads();
        // thread = one t-row (j), half of columns; 2B stores contiguous in t
        const int j  = tid & 127;
        const int chalf = tid >> 7;     // 0..1 -> columns [0,128) or [128,256)
        #pragma unroll 4
        for (int cg = 0; cg < 128; cg++) {
            const int c  = chalf * 128 + cg;
            const int nv = (n0 - 2048) + c;
            const int hh = nv >> 6, d = nv & 63;
            const float v = sf[j * 257 + c];
            __nv_bfloat16 h, l;
            split2(v, h, l);
            const size_t ob = ((size_t)(bb * H_ + hh) * DH + d) * T_ + t0 + j;
            g_vth[ob] = h;
            g_vtl[ob] = l;
        }
    }
}

// proj GEMM: plain fp32 epilogue to d_out
__global__ __launch_bounds__(256, 1)
void proj_gemm_tc(float* __restrict__ out)
{
    extern __shared__ __align__(128) char smem_raw[];
    const uint32_t smem = smem_u32(smem_raw);
    const int m0 = blockIdx.y * 128;
    const int n0 = blockIdx.x * 256;

    float acc[4][8][4];
    gemm_mainloop(g_yhi, g_ylo, g_wphi, g_wplo, m0, n0, smem, acc);

    const int lane = threadIdx.x & 31;
    const int warp = threadIdx.x >> 5;
    const int warp_m = warp & 1;
    const int warp_n = warp >> 1;
    const int g  = lane >> 2;
    const int tg = lane & 3;
    #pragma unroll
    for (int mt = 0; mt < 4; mt++) {
        #pragma unroll
        for (int nt = 0; nt < 8; nt++) {
            const int row = m0 + warp_m * 64 + mt * 16 + g;
            const int col = n0 + warp_n * 64 + nt * 8 + tg * 2;
            *(float2*)(out + (size_t)row * C_ + col) =
                make_float2(acc[mt][nt][0], acc[mt][nt][1]);
            *(float2*)(out + (size_t)(row + 8) * C_ + col) =
                make_float2(acc[mt][nt][2], acc[mt][nt][3]);
        }
    }
}

// ---------------------------------------------------------------------------
// HMMA flash attention (round-6 version, unchanged)
// ---------------------------------------------------------------------------
#define ATT_STAGE 32768
#define ATT_SMEM  (32768 + 3 * ATT_STAGE)

__global__ __launch_bounds__(128, 1)
void attn_hmma_kernel()
{
    extern __shared__ __align__(128) char smem_raw[];
    const uint32_t smem = smem_u32(smem_raw);
    const uint32_t qsm  = smem;
    const uint32_t st0  = smem + 32768;

    const int tid  = threadIdx.x;
    const int lane = tid & 31;
    const int warp = tid >> 5;
    const int qt   = (gridDim.x - 1) - blockIdx.x;
    const int bh   = blockIdx.z * H_ + blockIdx.y;
    const size_t qkb = (size_t)bh * T_ * DH;
    const size_t vb  = (size_t)bh * DH * T_;
    const int nkt = 2 * (qt + 1);

    {
        const __nv_bfloat16* s0 = g_qh + qkb + (size_t)qt * 128 * DH;
        const __nv_bfloat16* s1 = g_ql + qkb + (size_t)qt * 128 * DH;
        #pragma unroll
        for (int t = 0; t < 16; t++) {
            const int rem = ((t & 7) << 7) + tid;
            const int row = rem >> 3, ch = rem & 7;
            const __nv_bfloat16* g = ((t >> 3) ? s1 : s0) + (size_t)row * DH + ch * 8;
            cp16(qsm + (t >> 3) * 16384 + row * 128 + ((ch ^ (row & 7)) << 4), g);
        }
    }
    auto load_kv = [&](int kt, uint32_t stage) {
        #pragma unroll
        for (int t = 0; t < 16; t++) {
            const int mat = t >> 2;
            const int rem = ((t & 3) << 7) + tid;
            const int row = rem >> 3, ch = rem & 7;
            const __nv_bfloat16* g;
            if (mat == 0)      g = g_kh  + qkb + (size_t)(kt * 64 + row) * DH + ch * 8;
            else if (mat == 1) g = g_kl  + qkb + (size_t)(kt * 64 + row) * DH + ch * 8;
            else if (mat == 2) g = g_vth + vb  + (size_t)row * T_ + kt * 64 + ch * 8;
            else               g = g_vtl + vb  + (size_t)row * T_ + kt * 64 + ch * 8;
            cp16(stage + mat * 8192 + row * 128 + ((ch ^ (row & 7)) << 4), g);
        }
    };

    load_kv(0, st0);
    cp_commit();
    load_kv(1, st0 + ATT_STAGE);
    cp_commit();

    const int g   = lane >> 2;
    const int c2  = (lane & 3) * 2;
    const int q0w = qt * 128 + warp * 32;
    const int bkh = (lane >> 3) & 1;
    const int ah_ = lane >> 4;
    const int brow_base = ((lane >> 4) << 3) + (lane & 7);

    float O[2][8][4];
    #pragma unroll
    for (int mt = 0; mt < 2; mt++)
        #pragma unroll
        for (int nt = 0; nt < 8; nt++)
            #pragma unroll
            for (int i = 0; i < 4; i++) O[mt][nt][i] = 0.f;
    float mrun[2][2] = {{-1e30f, -1e30f}, {-1e30f, -1e30f}};
    float lrun[2][2] = {{0.f, 0.f}, {0.f, 0.f}};

    for (int kt = 0; kt < nkt; kt++) {
        cp_wait1();
        __syncthreads();

        const uint32_t nb = st0 + ((kt + 2) % 3) * ATT_STAGE;
        if (kt + 2 < nkt) load_kv(kt + 2, nb);
        else              cp16(nb + tid * 16, g_kh + tid * 8);
        cp_commit();

        const uint32_t sb = st0 + (kt % 3) * ATT_STAGE;

        float sacc[2][8][4];
        #pragma unroll
        for (int mt = 0; mt < 2; mt++)
            #pragma unroll
            for (int nt = 0; nt < 8; nt++)
                #pragma unroll
                for (int i = 0; i < 4; i++) sacc[mt][nt][i] = 0.f;

        #pragma unroll
        for (int kk = 0; kk < 4; kk++) {
            uint32_t qhf[2][4], qlf[2][4];
            #pragma unroll
            for (int mt = 0; mt < 2; mt++) {
                const int r = warp * 32 + mt * 16 + (lane & 15);
                const uint32_t off = r * 128 + ((((kk << 1) | ah_) ^ (r & 7)) << 4);
                LDSM4(qhf[mt], qsm + off);
                LDSM4(qlf[mt], qsm + 16384 + off);
            }
            uint32_t khf[8][2], klf[8][2];
            #pragma unroll
            for (int np = 0; np < 4; np++) {
                const int r = np * 16 + brow_base;
                const uint32_t off = r * 128 + ((((kk << 1) | bkh) ^ (r & 7)) << 4);
                uint32_t q4[4];
                LDSM4(q4, sb + off);
                khf[np * 2 + 0][0] = q4[0];  khf[np * 2 + 0][1] = q4[1];
                khf[np * 2 + 1][0] = q4[2];  khf[np * 2 + 1][1] = q4[3];
                LDSM4(q4, sb + 8192 + off);
                klf[np * 2 + 0][0] = q4[0];  klf[np * 2 + 0][1] = q4[1];
                klf[np * 2 + 1][0] = q4[2];  klf[np * 2 + 1][1] = q4[3];
            }
            #pragma unroll
            for (int mt = 0; mt < 2; mt++)
                #pragma unroll
                for (int nt = 0; nt < 8; nt++) {
                    mma16816(sacc[mt][nt], qhf[mt], khf[nt]);
                    mma16816(sacc[mt][nt], qhf[mt], klf[nt]);
                    mma16816(sacc[mt][nt], qlf[mt], khf[nt]);
                }
        }

        if (kt >= 2 * qt) {
            const int kt64 = kt * 64;
            #pragma unroll
            for (int mt = 0; mt < 2; mt++) {
                const int qr0 = q0w + mt * 16 + g;
                #pragma unroll
                for (int nt = 0; nt < 8; nt++) {
                    const int kc = kt64 + nt * 8 + c2;
                    if (kc > qr0)         sacc[mt][nt][0] = -1e30f;
                    if (kc + 1 > qr0)     sacc[mt][nt][1] = -1e30f;
                    if (kc > qr0 + 8)     sacc[mt][nt][2] = -1e30f;
                    if (kc + 1 > qr0 + 8) sacc[mt][nt][3] = -1e30f;
                }
            }
        }

        #pragma unroll
        for (int mt = 0; mt < 2; mt++) {
            float h0 = -1e30f, h1 = -1e30f;
            #pragma unroll
            for (int nt = 0; nt < 8; nt++) {
                h0 = fmaxf(h0, fmaxf(sacc[mt][nt][0], sacc[mt][nt][1]));
                h1 = fmaxf(h1, fmaxf(sacc[mt][nt][2], sacc[mt][nt][3]));
            }
            h0 = fmaxf(h0, __shfl_xor_sync(0xffffffffu, h0, 1));
            h0 = fmaxf(h0, __shfl_xor_sync(0xffffffffu, h0, 2));
            h1 = fmaxf(h1, __shfl_xor_sync(0xffffffffu, h1, 1));
            h1 = fmaxf(h1, __shfl_xor_sync(0xffffffffu, h1, 2));
            const float m0 = fmaxf(mrun[mt][0], h0);
            const float m1 = fmaxf(mrun[mt][1], h1);
            const float a0 = __expf(mrun[mt][0] - m0);
            const float a1 = __expf(mrun[mt][1] - m1);
            mrun[mt][0] = m0;  mrun[mt][1] = m1;

            float s0 = 0.f, s1 = 0.f;
            #pragma unroll
            for (int nt = 0; nt < 8; nt++) {
                float p0 = __expf(sacc[mt][nt][0] - m0);
                float p1 = __expf(sacc[mt][nt][1] - m0);
                float p2 = __expf(sacc[mt][nt][2] - m1);
                float p3 = __expf(sacc[mt][nt][3] - m1);
                sacc[mt][nt][0] = p0;  sacc[mt][nt][1] = p1;
                sacc[mt][nt][2] = p2;  sacc[mt][nt][3] = p3;
                s0 += p0 + p1;
                s1 += p2 + p3;
            }
            s0 += __shfl_xor_sync(0xffffffffu, s0, 1);
            s0 += __shfl_xor_sync(0xffffffffu, s0, 2);
            s1 += __shfl_xor_sync(0xffffffffu, s1, 1);
            s1 += __shfl_xor_sync(0xffffffffu, s1, 2);
            lrun[mt][0] = lrun[mt][0] * a0 + s0;
            lrun[mt][1] = lrun[mt][1] * a1 + s1;

            #pragma unroll
            for (int nt = 0; nt < 8; nt++) {
                O[mt][nt][0] *= a0;
                O[mt][nt][1] *= a0;
                O[mt][nt][2] *= a1;
                O[mt][nt][3] *= a1;
            }
        }

        #pragma unroll
        for (int kc = 0; kc < 4; kc++) {
            uint32_t ph[2][4], pl[2][4];
            #pragma unroll
            for (int mt = 0; mt < 2; mt++) {
                #pragma unroll
                for (int half = 0; half < 2; half++) {
                    const int nt = 2 * kc + half;
                    float p0 = sacc[mt][nt][0], p1 = sacc[mt][nt][1];
                    float p2 = sacc[mt][nt][2], p3 = sacc[mt][nt][3];
                    float h0 = __bfloat162float(__float2bfloat16(p0));
                    float h1 = __bfloat162float(__float2bfloat16(p1));
                    float h2 = __bfloat162float(__float2bfloat16(p2));
                    float h3 = __bfloat162float(__float2bfloat16(p3));
                    ph[mt][half * 2 + 0] = pack_bf16x2(h0, h1);
                    ph[mt][half * 2 + 1] = pack_bf16x2(h2, h3);
                    pl[mt][half * 2 + 0] = pack_bf16x2(p0 - h0, p1 - h1);
                    pl[mt][half * 2 + 1] = pack_bf16x2(p2 - h2, p3 - h3);
                }
            }
            uint32_t vh[8][2], vl[8][2];
            #pragma unroll
            for (int np = 0; np < 4; np++) {
                const int r = np * 16 + brow_base;
                const uint32_t off = r * 128 + ((((kc << 1) | bkh) ^ (r & 7)) << 4);
                uint32_t q4[4];
                LDSM4(q4, sb + 16384 + off);
                vh[np * 2 + 0][0] = q4[0];  vh[np * 2 + 0][1] = q4[1];
                vh[np * 2 + 1][0] = q4[2];  vh[np * 2 + 1][1] = q4[3];
                LDSM4(q4, sb + 24576 + off);
                vl[np * 2 + 0][0] = q4[0];  vl[np * 2 + 0][1] = q4[1];
                vl[np * 2 + 1][0] = q4[2];  vl[np * 2 + 1][1] = q4[3];
            }
            #pragma unroll
            for (int mt = 0; mt < 2; mt++)
                #pragma unroll
                for (int nt = 0; nt < 8; nt++) {
                    mma16816(O[mt][nt], ph[mt], vh[nt]);
                    mma16816(O[mt][nt], ph[mt], vl[nt]);
                    mma16816(O[mt][nt], pl[mt], vh[nt]);
                }
        }
    }

    const int hcol = blockIdx.y * 64;
    #pragma unroll
    for (int mt = 0; mt < 2; mt++) {
        const float inv0 = 1.f / lrun[mt][0];
        const float inv1 = 1.f / lrun[mt][1];
        const int r0 = blockIdx.z * T_ + q0w + mt * 16 + g;
        #pragma unroll
        for (int nt = 0; nt < 8; nt++) {
            const size_t o0 = (size_t)r0 * C_ + hcol + nt * 8 + c2;
            const size_t o1 = o0 + (size_t)8 * C_;
            __nv_bfloat16 h0, h1, h2, h3, l0, l1, l2, l3;
            split2(O[mt][nt][0] * inv0, h0, l0);
            split2(O[mt][nt][1] * inv0, h1, l1);
            split2(O[mt][nt][2] * inv1, h2, l2);
            split2(O[mt][nt][3] * inv1, h3, l3);
            *(__nv_bfloat162*)(g_yhi + o0) = __halves2bfloat162(h0, h1);
            *(__nv_bfloat162*)(g_ylo + o0) = __halves2bfloat162(l0, l1);
            *(__nv_bfloat162*)(g_yhi + o1) = __halves2bfloat162(h2, h3);
            *(__nv_bfloat162*)(g_ylo + o1) = __halves2bfloat162(l2, l3);
        }
    }
}

// ---------------------------------------------------------------------------
extern "C" void kernel_launch(void* const* d_in, const int* in_sizes, int n_in,
                              void* d_out, int out_size)
{
    const float* x      = (const float*)d_in[0];
    const float* w_attn = (const float*)d_in[1];
    const float* w_proj = (const float*)d_in[2];
    float* out = (float*)d_out;

    static bool attr_done = false;
    if (!attr_done) {
        cudaFuncSetAttribute(qkv_gemm_tc,  cudaFuncAttributeMaxDynamicSharedMemorySize, GEMM_SMEM);
        cudaFuncSetAttribute(proj_gemm_tc, cudaFuncAttributeMaxDynamicSharedMemorySize, GEMM_SMEM);
        cudaFuncSetAttribute(attn_hmma_kernel, cudaFuncAttributeMaxDynamicSharedMemorySize, ATT_SMEM);
        attr_done = true;
    }

    __nv_bfloat16 *xhi, *xlo, *wahi, *walo, *wphi, *wplo;
    cudaGetSymbolAddress((void**)&xhi,  g_xhi);
    cudaGetSymbolAddress((void**)&xlo,  g_xlo);
    cudaGetSymbolAddress((void**)&wahi, g_wahi);
    cudaGetSymbolAddress((void**)&walo, g_walo);
    cudaGetSymbolAddress((void**)&wphi, g_wphi);
    cudaGetSymbolAddress((void**)&wplo, g_wplo);

    // 1) split x -> bf16 hi/lo
    split_kernel<<<(M_ * KD) / 1024, 256>>>(x, xhi, xlo, M_ * KD);
    // 2) transpose+split weights
    {
        dim3 grid(KD / 32, (3 * C_) / 32);
        splitT_kernel<<<grid, dim3(32, 8)>>>(w_attn, wahi, walo, KD, 3 * C_);
    }
    {
        dim3 grid(KD / 32, C_ / 32);
        splitT_kernel<<<grid, dim3(32, 8)>>>(w_proj, wphi, wplo, KD, C_);
    }
    // 3) QKV GEMM (HMMA bf16x3, CTA 128x256) with fused head-major epilogue
    {
        dim3 grid((3 * C_) / 256, M_ / 128);
        qkv_gemm_tc<<<grid, 256, GEMM_SMEM>>>();
    }
    // 4) HMMA flash attention -> g_yhi/g_ylo
    {
        dim3 grid(T_ / 128, H_, B_);
        attn_hmma_kernel<<<grid, 128, ATT_SMEM>>>();
    }
    // 5) proj GEMM (HMMA bf16x3, CTA 128x256) -> out
    {
        dim3 grid(C_ / 256, M_ / 128);
        proj_gemm_tc<<<grid, 256, GEMM_SMEM>>>(out);
    }
}